// round 7
// baseline (speedup 1.0000x reference)
#include <cuda_runtime.h>
#include <cuda_bf16.h>
#include <cstdint>
#include <math.h>

// Problem constants
#define B_  2
#define L_  2048
#define NT  4096            // B*L tokens
#define D_  1024
#define H_  16
#define DH  64
#define D3  3072
#define EPS 1e-5f

// ---------------- scratch (device globals; no allocation) ----------------
__device__ __nv_bfloat16 g_hh[NT * D_];   // LN1 out hi
__device__ __nv_bfloat16 g_hl[NT * D_];   // LN1 out lo
__device__ __nv_bfloat16 g_wqh[D3 * D_];  // w_qkv hi
__device__ __nv_bfloat16 g_wql[D3 * D_];  // w_qkv lo
__device__ __nv_bfloat16 g_owh[D_ * D_];  // out_w hi
__device__ __nv_bfloat16 g_owl[D_ * D_];  // out_w lo
__device__ __nv_bfloat16 g_ch[NT * D_];   // ctx hi   [B,L,H,DH] == [NT,D]
__device__ __nv_bfloat16 g_cl[NT * D_];   // ctx lo
__device__ __nv_bfloat16 g_qh[NT * D_];   // q (scaled) hi  [BH,L,DH]
__device__ __nv_bfloat16 g_ql[NT * D_];
__device__ __nv_bfloat16 g_kh[NT * D_];   // k hi [BH,L,DH]
__device__ __nv_bfloat16 g_kl[NT * D_];
__device__ __nv_bfloat16 g_vth[NT * D_];  // v^T hi [BH,DH,L]
__device__ __nv_bfloat16 g_vtl[NT * D_];
__device__ float g_qkv[NT * D3];          // QKV gemm output [NT, 3D]
__device__ float g_cos[L_ * 32];
__device__ float g_sin[L_ * 32];

// ---------------- helpers ----------------
__device__ __forceinline__ uint32_t smem_u32(const void* p) {
    uint32_t a;
    asm("{ .reg .u64 t; cvta.to.shared.u64 t, %1; cvt.u32.u64 %0, t; }"
        : "=r"(a) : "l"(p));
    return a;
}
#define CP_ASYNC16(dst, src) \
    asm volatile("cp.async.cg.shared.global [%0], [%1], 16;" :: "r"(dst), "l"(src))
#define CP_COMMIT() asm volatile("cp.async.commit_group;" ::: "memory")
#define CP_WAIT0()  asm volatile("cp.async.wait_group 0;" ::: "memory")
#define CP_WAIT1()  asm volatile("cp.async.wait_group 1;" ::: "memory")

// mma.sync m16n8k16 bf16 -> fp32 (legacy HMMA path, valid on compute_103)
#define MMA16816(d, a, b) \
    asm volatile( \
        "mma.sync.aligned.m16n8k16.row.col.f32.bf16.bf16.f32 " \
        "{%0,%1,%2,%3}, {%4,%5,%6,%7}, {%8,%9}, {%0,%1,%2,%3};" \
        : "+f"((d)[0]), "+f"((d)[1]), "+f"((d)[2]), "+f"((d)[3]) \
        : "r"((a)[0]), "r"((a)[1]), "r"((a)[2]), "r"((a)[3]), \
          "r"((b)[0]), "r"((b)[1]))

// ldmatrix x4 (b16, no trans)
#define LDM_X4(r0, r1, r2, r3, addr) \
    asm volatile("ldmatrix.sync.aligned.m8n8.x4.shared.b16 {%0,%1,%2,%3}, [%4];" \
        : "=r"(r0), "=r"(r1), "=r"(r2), "=r"(r3) : "r"(addr))

// ---------------- RoPE table ----------------
__global__ void rope_table_kernel() {
    int idx = blockIdx.x * blockDim.x + threadIdx.x;
    if (idx >= L_ * 32) return;
    int l = idx >> 5;
    int j = idx & 31;
    float inv = powf(10000.0f, -(float)j / 32.0f);
    float ang = (float)l * inv;
    float s, c;
    sincosf(ang, &s, &c);
    g_cos[idx] = c;
    g_sin[idx] = s;
}

// ---------------- hi/lo bf16 split for weights ----------------
__global__ void split_kernel(const float* __restrict__ x,
                             __nv_bfloat16* __restrict__ hi,
                             __nv_bfloat16* __restrict__ lo) {
    int i = (blockIdx.x * 256 + threadIdx.x) * 4;
    float4 v = *(const float4*)&x[i];
    float vv[4] = {v.x, v.y, v.z, v.w};
    union { __nv_bfloat16 h[4]; uint2 u; } a, b;
    #pragma unroll
    for (int j = 0; j < 4; j++) {
        __nv_bfloat16 hb = __float2bfloat16(vv[j]);
        a.h[j] = hb;
        b.h[j] = __float2bfloat16(vv[j] - __bfloat162float(hb));
    }
    *(uint2*)&hi[i] = a.u;
    *(uint2*)&lo[i] = b.u;
}

// ---------------- LN1 -> bf16 hi/lo ----------------
__global__ void ln1_kernel(const float* __restrict__ x,
                           const float* __restrict__ w,
                           const float* __restrict__ b) {
    int n = blockIdx.x;
    const float* xr = x + (size_t)n * D_;
    int t = threadIdx.x;
    float4 v = *(const float4*)&xr[t * 4];
    float s  = v.x + v.y + v.z + v.w;
    float s2 = v.x*v.x + v.y*v.y + v.z*v.z + v.w*v.w;
    #pragma unroll
    for (int o = 16; o >= 1; o >>= 1) {
        s  += __shfl_xor_sync(0xffffffffu, s,  o);
        s2 += __shfl_xor_sync(0xffffffffu, s2, o);
    }
    __shared__ float red[2][8];
    int lane = t & 31, wp = t >> 5;
    if (lane == 0) { red[0][wp] = s; red[1][wp] = s2; }
    __syncthreads();
    __shared__ float stat[2];
    if (t == 0) {
        float a = 0.f, c = 0.f;
        #pragma unroll
        for (int i = 0; i < 8; i++) { a += red[0][i]; c += red[1][i]; }
        float mu  = a * (1.0f / D_);
        float var = c * (1.0f / D_) - mu * mu;
        stat[0] = mu;
        stat[1] = rsqrtf(var + EPS);
    }
    __syncthreads();
    float mu = stat[0], rs = stat[1];
    float4 wv = *(const float4*)&w[t * 4];
    float4 bv = *(const float4*)&b[t * 4];
    float oo[4];
    oo[0] = (v.x - mu) * rs * wv.x + bv.x;
    oo[1] = (v.y - mu) * rs * wv.y + bv.y;
    oo[2] = (v.z - mu) * rs * wv.z + bv.z;
    oo[3] = (v.w - mu) * rs * wv.w + bv.w;
    union { __nv_bfloat16 h[4]; uint2 u; } a, bb;
    #pragma unroll
    for (int j = 0; j < 4; j++) {
        __nv_bfloat16 hb = __float2bfloat16(oo[j]);
        a.h[j]  = hb;
        bb.h[j] = __float2bfloat16(oo[j] - __bfloat162float(hb));
    }
    size_t oidx = (size_t)n * D_ + t * 4;
    *(uint2*)&g_hh[oidx] = a.u;
    *(uint2*)&g_hl[oidx] = bb.u;
}

// ============ warp-MMA bf16 split-3 GEMM v2 ============
// CTA 128x128, 8 warps of 64x32, K-step 16, 3-stage cp.async, ldmatrix loads.
// Smem rows padded to 24 bf16 (48B) -> ldmatrix conflict-free.
#define GSTR   24                       // bf16 elems per padded row
#define GSPLIT (128 * GSTR * 2)         // bytes per split buffer (6144)
#define GSTAGE (2 * GSPLIT)             // bytes per stage (hi+lo)   (12288)

__global__ __launch_bounds__(256) void gemm_mma(
    const __nv_bfloat16* __restrict__ Ah, const __nv_bfloat16* __restrict__ Al,
    const __nv_bfloat16* __restrict__ Bh, const __nv_bfloat16* __restrict__ Bl,
    float* __restrict__ C, int M, int N, int K)
{
    __shared__ __nv_bfloat16 sA[3 * GSTAGE / 2];
    __shared__ __nv_bfloat16 sB[3 * GSTAGE / 2];
    const uint32_t uA = smem_u32(sA), uB = smem_u32(sB);

    int tid = threadIdx.x;
    int warp = tid >> 5, lane = tid & 31;
    int m0 = blockIdx.y * 128, n0 = blockIdx.x * 128;
    int wm = (warp & 1) * 64, wn = (warp >> 1) * 32;

    int lrow = tid >> 1;              // 0..127
    int half = tid & 1;               // 16B chunk within 32B row-slice
    uint32_t dsto = (uint32_t)(lrow * 48 + half * 16);

    const __nv_bfloat16* gA[2] = {Ah + (size_t)(m0 + lrow) * K + half * 8,
                                  Al + (size_t)(m0 + lrow) * K + half * 8};
    const __nv_bfloat16* gB[2] = {Bh + (size_t)(n0 + lrow) * K + half * 8,
                                  Bl + (size_t)(n0 + lrow) * K + half * 8};

    float d[4][4][4];
    #pragma unroll
    for (int mi = 0; mi < 4; mi++)
        #pragma unroll
        for (int ni = 0; ni < 4; ni++)
            #pragma unroll
            for (int r = 0; r < 4; r++) d[mi][ni][r] = 0.f;

    const int nstep = K >> 4;

    // prologue: stages 0,1
    #pragma unroll
    for (int s = 0; s < 2; s++) {
        #pragma unroll
        for (int sp = 0; sp < 2; sp++) {
            CP_ASYNC16(uA + s * GSTAGE + sp * GSPLIT + dsto, gA[sp] + s * 16);
            CP_ASYNC16(uB + s * GSTAGE + sp * GSPLIT + dsto, gB[sp] + s * 16);
        }
        CP_COMMIT();
    }

    // ldmatrix lane addresses (within a split buffer)
    uint32_t aoff = (uint32_t)((wm + (lane & 15)) * 48 + (lane >> 4) * 16);
    uint32_t boff = (uint32_t)((wn + (lane & 15)) * 48 + (lane >> 4) * 16);

    for (int s = 0; s < nstep; s++) {
        int st = s % 3;
        if (s == nstep - 1) { CP_WAIT0(); } else { CP_WAIT1(); }
        __syncthreads();

        if (s + 2 < nstep) {
            int sn = (s + 2) % 3;
            #pragma unroll
            for (int sp = 0; sp < 2; sp++) {
                CP_ASYNC16(uA + sn * GSTAGE + sp * GSPLIT + dsto, gA[sp] + (s + 2) * 16);
                CP_ASYNC16(uB + sn * GSTAGE + sp * GSPLIT + dsto, gB[sp] + (s + 2) * 16);
            }
            CP_COMMIT();
        }

        uint32_t ah[4][4], al[4][4], bh[4][2], bl[4][2];
        uint32_t aHi = uA + st * GSTAGE + aoff;
        uint32_t aLo = aHi + GSPLIT;
        uint32_t bHi = uB + st * GSTAGE + boff;
        uint32_t bLo = bHi + GSPLIT;
        #pragma unroll
        for (int mi = 0; mi < 4; mi++) {
            LDM_X4(ah[mi][0], ah[mi][1], ah[mi][2], ah[mi][3], aHi + mi * 16 * 48);
            LDM_X4(al[mi][0], al[mi][1], al[mi][2], al[mi][3], aLo + mi * 16 * 48);
        }
        #pragma unroll
        for (int np = 0; np < 2; np++) {
            uint32_t t0, t1, t2, t3;
            LDM_X4(t0, t1, t2, t3, bHi + np * 16 * 48);
            bh[2*np][0] = t0; bh[2*np+1][0] = t1; bh[2*np][1] = t2; bh[2*np+1][1] = t3;
            LDM_X4(t0, t1, t2, t3, bLo + np * 16 * 48);
            bl[2*np][0] = t0; bl[2*np+1][0] = t1; bl[2*np][1] = t2; bl[2*np+1][1] = t3;
        }

        #pragma unroll
        for (int mi = 0; mi < 4; mi++)
            #pragma unroll
            for (int ni = 0; ni < 4; ni++) {
                MMA16816(d[mi][ni], ah[mi], bh[ni]);
                MMA16816(d[mi][ni], ah[mi], bl[ni]);
                MMA16816(d[mi][ni], al[mi], bh[ni]);
            }
    }

    #pragma unroll
    for (int mi = 0; mi < 4; mi++) {
        int r = m0 + wm + mi * 16 + (lane >> 2);
        #pragma unroll
        for (int ni = 0; ni < 4; ni++) {
            int c = n0 + wn + ni * 8 + (lane & 3) * 2;
            *(float2*)&C[(size_t)r * N + c] = make_float2(d[mi][ni][0], d[mi][ni][1]);
            *(float2*)&C[(size_t)(r + 8) * N + c] = make_float2(d[mi][ni][2], d[mi][ni][3]);
        }
    }
}

// ---------------- fused QK-LN + RoPE -> bf16 hi/lo [BH,L,DH] ----------------
__global__ void qk_rope_kernel(const float* __restrict__ qw,
                               const float* __restrict__ kw) {
    int n = blockIdx.x;
    int b = n >> 11;
    int l = n & 2047;
    const float* q = g_qkv + (size_t)n * D3;
    const float* k = q + D_;
    int t = threadIdx.x;

    float4 qv = *(const float4*)&q[t * 4];
    float4 kv = *(const float4*)&k[t * 4];
    float qs  = qv.x + qv.y + qv.z + qv.w;
    float qs2 = qv.x*qv.x + qv.y*qv.y + qv.z*qv.z + qv.w*qv.w;
    float ks  = kv.x + kv.y + kv.z + kv.w;
    float ks2 = kv.x*kv.x + kv.y*kv.y + kv.z*kv.z + kv.w*kv.w;
    #pragma unroll
    for (int o = 16; o >= 1; o >>= 1) {
        qs  += __shfl_xor_sync(0xffffffffu, qs,  o);
        qs2 += __shfl_xor_sync(0xffffffffu, qs2, o);
        ks  += __shfl_xor_sync(0xffffffffu, ks,  o);
        ks2 += __shfl_xor_sync(0xffffffffu, ks2, o);
    }
    __shared__ float red[4][8];
    __shared__ float stat[4];
    __shared__ float qn[D_], kn[D_];
    int lane = t & 31, wp = t >> 5;
    if (lane == 0) { red[0][wp]=qs; red[1][wp]=qs2; red[2][wp]=ks; red[3][wp]=ks2; }
    __syncthreads();
    if (t == 0) {
        float a=0,c=0,e=0,f=0;
        #pragma unroll
        for (int i=0;i<8;i++){a+=red[0][i];c+=red[1][i];e+=red[2][i];f+=red[3][i];}
        float qmu=a*(1.f/D_), qvr=c*(1.f/D_)-qmu*qmu;
        float kmu=e*(1.f/D_), kvr=f*(1.f/D_)-kmu*kmu;
        stat[0]=qmu; stat[1]=rsqrtf(qvr+EPS);
        stat[2]=kmu; stat[3]=rsqrtf(kvr+EPS);
    }
    __syncthreads();
    float qmu=stat[0], qrs=stat[1], kmu=stat[2], krs=stat[3];
    float4 qwv = *(const float4*)&qw[t*4];
    float4 kwv = *(const float4*)&kw[t*4];
    qn[t*4+0]=(qv.x-qmu)*qrs*qwv.x; qn[t*4+1]=(qv.y-qmu)*qrs*qwv.y;
    qn[t*4+2]=(qv.z-qmu)*qrs*qwv.z; qn[t*4+3]=(qv.w-qmu)*qrs*qwv.w;
    kn[t*4+0]=(kv.x-kmu)*krs*kwv.x; kn[t*4+1]=(kv.y-kmu)*krs*kwv.y;
    kn[t*4+2]=(kv.z-kmu)*krs*kwv.z; kn[t*4+3]=(kv.w-kmu)*krs*kwv.w;
    __syncthreads();

    int d0 = t * 4;
    int hh = d0 >> 6;
    int j0 = d0 & 63;
    float qo[4], ko[4];
    #pragma unroll
    for (int ii = 0; ii < 4; ii++) {
        int d = d0 + ii;
        int j = j0 + ii;
        int f = j & 31;
        float c = g_cos[l * 32 + f];
        float s = g_sin[l * 32 + f];
        if (j < 32) {
            qo[ii] = qn[d] * c - qn[d + 32] * s;
            ko[ii] = kn[d] * c - kn[d + 32] * s;
        } else {
            qo[ii] = qn[d] * c + qn[d - 32] * s;
            ko[ii] = kn[d] * c + kn[d - 32] * s;
        }
        qo[ii] *= 0.125f;   // fold softmax scale into q
    }
    size_t oidx = (((size_t)(b * H_ + hh)) * L_ + l) * DH + j0;
    union { __nv_bfloat16 h[4]; uint2 u; } uqh, uql, ukh, ukl;
    #pragma unroll
    for (int ii = 0; ii < 4; ii++) {
        __nv_bfloat16 hb = __float2bfloat16(qo[ii]);
        uqh.h[ii] = hb;
        uql.h[ii] = __float2bfloat16(qo[ii] - __bfloat162float(hb));
        __nv_bfloat16 kb = __float2bfloat16(ko[ii]);
        ukh.h[ii] = kb;
        ukl.h[ii] = __float2bfloat16(ko[ii] - __bfloat162float(kb));
    }
    *(uint2*)&g_qh[oidx] = uqh.u;
    *(uint2*)&g_ql[oidx] = uql.u;
    *(uint2*)&g_kh[oidx] = ukh.u;
    *(uint2*)&g_kl[oidx] = ukl.u;
}

// ---------------- V transpose: g_qkv v-part -> [BH,DH,L] bf16 hi/lo ----------------
__global__ void vt_kernel() {
    __shared__ float tile[64][33];
    int bh = blockIdx.y;
    int b = bh >> 4, h = bh & 15;
    int l0 = blockIdx.x * 32;
    int tx = threadIdx.x & 31, ty = threadIdx.x >> 5;   // 256 threads

    #pragma unroll
    for (int i = 0; i < 4; i++) {
        int l = l0 + ty + i * 8;
        const float* row = g_qkv + (size_t)(b * L_ + l) * D3 + 2 * D_ + h * DH;
        tile[tx][ty + i * 8]      = row[tx];
        tile[tx + 32][ty + i * 8] = row[tx + 32];
    }
    __syncthreads();
    #pragma unroll
    for (int i = 0; i < 8; i++) {
        int d = ty + i * 8;
        float v = tile[d][tx];
        __nv_bfloat16 hb = __float2bfloat16(v);
        __nv_bfloat16 lb = __float2bfloat16(v - __bfloat162float(hb));
        size_t o = (size_t)(bh * DH + d) * L_ + l0 + tx;
        g_vth[o] = hb;
        g_vtl[o] = lb;
    }
}

// ---------------- flash attention on mma.sync (bf16 split-3, ldmatrix) ----------------
#define KPAD 72
#define AT_SM_QH 0
#define AT_SM_QL 9216
#define AT_SM_KV 18432
#define AT_SM_TILE 9216
#define AT_SM_BUF 36864
#define AT_SM_SK (18432 + 2 * 36864)
#define ATT2_SMEM (AT_SM_SK + 512)

__global__ __launch_bounds__(128) void attn_mma(const int* __restrict__ seq_id) {
    extern __shared__ char sm[];
    const uint32_t sbase = smem_u32(sm);
    int tid = threadIdx.x, lane = tid & 31, w = tid >> 5;
    int qt = blockIdx.x, h = blockIdx.y, b = blockIdx.z;
    int bh = b * H_ + h;
    int row0 = qt * 64;

    const __nv_bfloat16* gQh = g_qh + ((size_t)bh * L_ + row0) * DH;
    const __nv_bfloat16* gQl = g_ql + ((size_t)bh * L_ + row0) * DH;
    const __nv_bfloat16* gKh = g_kh + (size_t)bh * L_ * DH;
    const __nv_bfloat16* gKl = g_kl + (size_t)bh * L_ * DH;
    const __nv_bfloat16* gVh = g_vth + (size_t)bh * DH * L_;
    const __nv_bfloat16* gVl = g_vtl + (size_t)bh * DH * L_;

    int lrow = tid >> 1;          // 0..63
    int cb0  = (tid & 1) * 4;     // chunk base (16B chunks)

    // ---- prologue: Q tiles ----
    #pragma unroll
    for (int c = 0; c < 4; c++) {
        int ch = cb0 + c;
        uint32_t so = (uint32_t)(lrow * KPAD + ch * 8) * 2;
        CP_ASYNC16(sbase + AT_SM_QH + so, gQh + lrow * DH + ch * 8);
        CP_ASYNC16(sbase + AT_SM_QL + so, gQl + lrow * DH + ch * 8);
    }
    CP_COMMIT();
    // ---- K/V tile 0 ----
    {
        uint32_t dst = sbase + AT_SM_KV;
        #pragma unroll
        for (int c = 0; c < 4; c++) {
            int ch = cb0 + c;
            uint32_t so = (uint32_t)(lrow * KPAD + ch * 8) * 2;
            CP_ASYNC16(dst + so,                  gKh + (size_t)lrow * DH + ch * 8);
            CP_ASYNC16(dst + AT_SM_TILE + so,     gKl + (size_t)lrow * DH + ch * 8);
            CP_ASYNC16(dst + 2 * AT_SM_TILE + so, gVh + (size_t)lrow * L_ + ch * 8);
            CP_ASYNC16(dst + 3 * AT_SM_TILE + so, gVl + (size_t)lrow * L_ + ch * 8);
        }
    }
    CP_COMMIT();
    if (tid < 64) ((int*)(sm + AT_SM_SK))[tid] = seq_id[b * L_ + tid];
    int sq0 = seq_id[b * L_ + row0 + w * 16 + (lane >> 2)];
    int sq1 = seq_id[b * L_ + row0 + w * 16 + (lane >> 2) + 8];

    CP_WAIT1();
    __syncthreads();

    // ---- extract Q fragments (held for whole kernel) ----
    uint32_t qfh[4][4], qfl[4][4];
    {
        uint32_t qoff = (uint32_t)((w * 16 + (lane & 15)) * KPAD * 2 + (lane >> 4) * 16);
        #pragma unroll
        for (int s = 0; s < 4; s++) {
            LDM_X4(qfh[s][0], qfh[s][1], qfh[s][2], qfh[s][3],
                   sbase + AT_SM_QH + qoff + s * 32);
            LDM_X4(qfl[s][0], qfl[s][1], qfl[s][2], qfl[s][3],
                   sbase + AT_SM_QL + qoff + s * 32);
        }
    }

    float m0 = -1e30f, m1 = -1e30f, l0 = 0.f, l1 = 0.f;
    float pv[8][4];
    #pragma unroll
    for (int j = 0; j < 8; j++)
        #pragma unroll
        for (int r = 0; r < 4; r++) pv[j][r] = 0.f;

    // ldmatrix lane base for K/V fragments
    uint32_t kvoff = (uint32_t)((lane & 15) * KPAD * 2 + (lane >> 4) * 16);

    for (int it = 0; it < L_ / 64; it++) {
        int buf = it & 1;
        CP_WAIT0();
        __syncthreads();

        // prefetch next tile into other buffer
        if (it + 1 < L_ / 64) {
            int col0n = (it + 1) * 64;
            uint32_t dst = sbase + AT_SM_KV + (buf ^ 1) * AT_SM_BUF;
            #pragma unroll
            for (int c = 0; c < 4; c++) {
                int ch = cb0 + c;
                uint32_t so = (uint32_t)(lrow * KPAD + ch * 8) * 2;
                CP_ASYNC16(dst + so,                  gKh + (size_t)(col0n + lrow) * DH + ch * 8);
                CP_ASYNC16(dst + AT_SM_TILE + so,     gKl + (size_t)(col0n + lrow) * DH + ch * 8);
                CP_ASYNC16(dst + 2 * AT_SM_TILE + so, gVh + (size_t)lrow * L_ + col0n + ch * 8);
                CP_ASYNC16(dst + 3 * AT_SM_TILE + so, gVl + (size_t)lrow * L_ + col0n + ch * 8);
            }
            if (tid < 64)
                ((int*)(sm + AT_SM_SK))[(buf ^ 1) * 64 + tid] =
                    seq_id[b * L_ + col0n + tid];
        }
        CP_COMMIT();

        uint32_t uKh = sbase + AT_SM_KV + buf * AT_SM_BUF + kvoff;
        uint32_t uKl = uKh + AT_SM_TILE;
        uint32_t uVh = uKh + 2 * AT_SM_TILE;
        uint32_t uVl = uKh + 3 * AT_SM_TILE;
        const int* skp = (const int*)(sm + AT_SM_SK) + buf * 64;

        // ---- S = Q K^T (split-3, ldmatrix) ----
        float sf[8][4];
        #pragma unroll
        for (int j = 0; j < 8; j++)
            #pragma unroll
            for (int r = 0; r < 4; r++) sf[j][r] = 0.f;
        #pragma unroll
        for (int s = 0; s < 4; s++) {
            #pragma unroll
            for (int jp = 0; jp < 4; jp++) {
                uint32_t ad = jp * 16 * (KPAD * 2) + s * 32;
                uint32_t h0, h1, h2, h3, e0, e1, e2, e3;
                LDM_X4(h0, h1, h2, h3, uKh + ad);
                LDM_X4(e0, e1, e2, e3, uKl + ad);
                uint32_t bh0[2] = {h0, h2}, bh1[2] = {h1, h3};
                uint32_t bl0[2] = {e0, e2}, bl1[2] = {e1, e3};
                MMA16816(sf[2*jp],   qfh[s], bh0);
                MMA16816(sf[2*jp],   qfh[s], bl0);
                MMA16816(sf[2*jp],   qfl[s], bh0);
                MMA16816(sf[2*jp+1], qfh[s], bh1);
                MMA16816(sf[2*jp+1], qfh[s], bl1);
                MMA16816(sf[2*jp+1], qfl[s], bh1);
            }
        }

        // ---- mask + online softmax (c-frag layout) ----
        int colb = (lane & 3) * 2;
        float nm0 = m0, nm1 = m1;
        #pragma unroll
        for (int j = 0; j < 8; j++) {
            int k0 = skp[8 * j + colb], k1 = skp[8 * j + colb + 1];
            sf[j][0] = (k0 == sq0) ? sf[j][0] : -2e30f;
            sf[j][1] = (k1 == sq0) ? sf[j][1] : -2e30f;
            sf[j][2] = (k0 == sq1) ? sf[j][2] : -2e30f;
            sf[j][3] = (k1 == sq1) ? sf[j][3] : -2e30f;
            nm0 = fmaxf(nm0, fmaxf(sf[j][0], sf[j][1]));
            nm1 = fmaxf(nm1, fmaxf(sf[j][2], sf[j][3]));
        }
        nm0 = fmaxf(nm0, __shfl_xor_sync(0xffffffffu, nm0, 1));
        nm0 = fmaxf(nm0, __shfl_xor_sync(0xffffffffu, nm0, 2));
        nm1 = fmaxf(nm1, __shfl_xor_sync(0xffffffffu, nm1, 1));
        nm1 = fmaxf(nm1, __shfl_xor_sync(0xffffffffu, nm1, 2));
        float a0 = __expf(m0 - nm0), a1 = __expf(m1 - nm1);
        m0 = nm0; m1 = nm1;

        float s0 = 0.f, s1 = 0.f;
        uint32_t ph[4][4], pl[4][4];
        #pragma unroll
        for (int j = 0; j < 8; j++) {
            float p0 = __expf(sf[j][0] - m0), p1 = __expf(sf[j][1] - m0);
            float p2 = __expf(sf[j][2] - m1), p3 = __expf(sf[j][3] - m1);
            s0 += p0 + p1; s1 += p2 + p3;
            __nv_bfloat162 h01 = __float22bfloat162_rn(make_float2(p0, p1));
            float2 f01 = __bfloat1622float2(h01);
            __nv_bfloat162 l01 = __float22bfloat162_rn(make_float2(p0 - f01.x, p1 - f01.y));
            __nv_bfloat162 h23 = __float22bfloat162_rn(make_float2(p2, p3));
            float2 f23 = __bfloat1622float2(h23);
            __nv_bfloat162 l23 = __float22bfloat162_rn(make_float2(p2 - f23.x, p3 - f23.y));
            int s_ = j >> 1;
            int o  = (j & 1) * 2;
            ph[s_][o]     = *(uint32_t*)&h01;
            ph[s_][o + 1] = *(uint32_t*)&h23;
            pl[s_][o]     = *(uint32_t*)&l01;
            pl[s_][o + 1] = *(uint32_t*)&l23;
        }
        s0 += __shfl_xor_sync(0xffffffffu, s0, 1);
        s0 += __shfl_xor_sync(0xffffffffu, s0, 2);
        s1 += __shfl_xor_sync(0xffffffffu, s1, 1);
        s1 += __shfl_xor_sync(0xffffffffu, s1, 2);
        l0 = l0 * a0 + s0;
        l1 = l1 * a1 + s1;
        #pragma unroll
        for (int j = 0; j < 8; j++) {
            pv[j][0] *= a0; pv[j][1] *= a0; pv[j][2] *= a1; pv[j][3] *= a1;
        }

        // ---- PV (split-3, ldmatrix), B = Vt[dh][c] ----
        #pragma unroll
        for (int s = 0; s < 4; s++) {
            #pragma unroll
            for (int jp = 0; jp < 4; jp++) {
                uint32_t ad = jp * 16 * (KPAD * 2) + s * 32;
                uint32_t h0, h1, h2, h3, e0, e1, e2, e3;
                LDM_X4(h0, h1, h2, h3, uVh + ad);
                LDM_X4(e0, e1, e2, e3, uVl + ad);
                uint32_t bh0[2] = {h0, h2}, bh1[2] = {h1, h3};
                uint32_t bl0[2] = {e0, e2}, bl1[2] = {e1, e3};
                MMA16816(pv[2*jp],   ph[s], bh0);
                MMA16816(pv[2*jp],   ph[s], bl0);
                MMA16816(pv[2*jp],   pl[s], bh0);
                MMA16816(pv[2*jp+1], ph[s], bh1);
                MMA16816(pv[2*jp+1], ph[s], bl1);
                MMA16816(pv[2*jp+1], pl[s], bh1);
            }
        }
    }

    // ---- epilogue: ctx / l -> bf16 hi/lo [B,L,H,DH] ----
    float inv0 = 1.0f / l0, inv1 = 1.0f / l1;
    int r0g = row0 + w * 16 + (lane >> 2);
    #pragma unroll
    for (int j = 0; j < 8; j++) {
        int c = 8 * j + (lane & 3) * 2;
        size_t o0 = (((size_t)b * L_ + r0g) * H_ + h) * DH + c;
        size_t o1 = (((size_t)b * L_ + r0g + 8) * H_ + h) * DH + c;
        float x0 = pv[j][0] * inv0, x1 = pv[j][1] * inv0;
        float y0 = pv[j][2] * inv1, y1 = pv[j][3] * inv1;
        __nv_bfloat162 hx = __float22bfloat162_rn(make_float2(x0, x1));
        float2 fx = __bfloat1622float2(hx);
        __nv_bfloat162 lx = __float22bfloat162_rn(make_float2(x0 - fx.x, x1 - fx.y));
        __nv_bfloat162 hy = __float22bfloat162_rn(make_float2(y0, y1));
        float2 fy = __bfloat1622float2(hy);
        __nv_bfloat162 ly = __float22bfloat162_rn(make_float2(y0 - fy.x, y1 - fy.y));
        *(uint32_t*)&g_ch[o0] = *(uint32_t*)&hx;
        *(uint32_t*)&g_cl[o0] = *(uint32_t*)&lx;
        *(uint32_t*)&g_ch[o1] = *(uint32_t*)&hy;
        *(uint32_t*)&g_cl[o1] = *(uint32_t*)&ly;
    }
}

// ---------------- launch ----------------
extern "C" void kernel_launch(void* const* d_in, const int* in_sizes, int n_in,
                              void* d_out, int out_size) {
    const float* x      = (const float*)d_in[0];
    const int*   seq_id = (const int*)  d_in[1];
    const float* ln1_w  = (const float*)d_in[2];
    const float* ln1_b  = (const float*)d_in[3];
    const float* w_qkv  = (const float*)d_in[4];
    const float* q_ln_w = (const float*)d_in[5];
    const float* k_ln_w = (const float*)d_in[6];
    const float* out_w  = (const float*)d_in[7];
    float* out = (float*)d_out;

    void *phh, *phl, *pwqh, *pwql, *powh, *powl, *pch, *pcl, *pqkv;
    cudaGetSymbolAddress(&phh,  g_hh);
    cudaGetSymbolAddress(&phl,  g_hl);
    cudaGetSymbolAddress(&pwqh, g_wqh);
    cudaGetSymbolAddress(&pwql, g_wql);
    cudaGetSymbolAddress(&powh, g_owh);
    cudaGetSymbolAddress(&powl, g_owl);
    cudaGetSymbolAddress(&pch,  g_ch);
    cudaGetSymbolAddress(&pcl,  g_cl);
    cudaGetSymbolAddress(&pqkv, g_qkv);

    cudaFuncSetAttribute(attn_mma, cudaFuncAttributeMaxDynamicSharedMemorySize,
                         ATT2_SMEM);

    rope_table_kernel<<<(L_ * 32 + 255) / 256, 256>>>();
    split_kernel<<<(D3 * D_) / 1024, 256>>>(w_qkv, (__nv_bfloat16*)pwqh,
                                            (__nv_bfloat16*)pwql);
    split_kernel<<<(D_ * D_) / 1024, 256>>>(out_w, (__nv_bfloat16*)powh,
                                            (__nv_bfloat16*)powl);
    ln1_kernel<<<NT, 256>>>(x, ln1_w, ln1_b);
    gemm_mma<<<dim3(D3 / 128, NT / 128), 256>>>(
        (const __nv_bfloat16*)phh, (const __nv_bfloat16*)phl,
        (const __nv_bfloat16*)pwqh, (const __nv_bfloat16*)pwql,
        (float*)pqkv, NT, D3, D_);
    qk_rope_kernel<<<NT, 256>>>(q_ln_w, k_ln_w);
    vt_kernel<<<dim3(L_ / 32, B_ * H_), 256>>>();
    attn_mma<<<dim3(L_ / 64, H_, B_), 128, ATT2_SMEM>>>(seq_id);
    gemm_mma<<<dim3(D_ / 128, NT / 128), 256>>>(
        (const __nv_bfloat16*)pch, (const __nv_bfloat16*)pcl,
        (const __nv_bfloat16*)powh, (const __nv_bfloat16*)powl,
        out, NT, D_, D_);
}

// round 8
// speedup vs baseline: 1.5695x; 1.5695x over previous
#include <cuda_runtime.h>
#include <cuda_bf16.h>
#include <cstdint>
#include <math.h>

// Problem constants
#define B_  2
#define L_  2048
#define NT  4096            // B*L tokens
#define D_  1024
#define H_  16
#define DH  64
#define D3  3072
#define EPS 1e-5f

// ---------------- scratch (device globals; no allocation) ----------------
__device__ __nv_bfloat16 g_hh[NT * D_];   // LN1 out hi
__device__ __nv_bfloat16 g_hl[NT * D_];   // LN1 out lo
__device__ __nv_bfloat16 g_wqh[D3 * D_];  // w_qkv hi
__device__ __nv_bfloat16 g_wql[D3 * D_];  // w_qkv lo
__device__ __nv_bfloat16 g_owh[D_ * D_];  // out_w hi
__device__ __nv_bfloat16 g_owl[D_ * D_];  // out_w lo
__device__ __nv_bfloat16 g_ch[NT * D_];   // ctx hi   [B,L,H,DH] == [NT,D]
__device__ __nv_bfloat16 g_cl[NT * D_];   // ctx lo
__device__ __nv_bfloat16 g_qh[NT * D_];   // q (scaled) hi  [BH,L,DH]
__device__ __nv_bfloat16 g_ql[NT * D_];
__device__ __nv_bfloat16 g_kh[NT * D_];   // k hi [BH,L,DH]
__device__ __nv_bfloat16 g_kl[NT * D_];
__device__ __nv_bfloat16 g_vth[NT * D_];  // v^T hi [BH,DH,L]
__device__ __nv_bfloat16 g_vtl[NT * D_];
__device__ float g_qkv[NT * D3];          // QKV gemm output [NT, 3D]
__device__ float g_cos[L_ * 32];
__device__ float g_sin[L_ * 32];

// ---------------- helpers ----------------
__device__ __forceinline__ uint32_t smem_u32(const void* p) {
    uint32_t a;
    asm("{ .reg .u64 t; cvta.to.shared.u64 t, %1; cvt.u32.u64 %0, t; }"
        : "=r"(a) : "l"(p));
    return a;
}
#define CP_ASYNC16(dst, src) \
    asm volatile("cp.async.cg.shared.global [%0], [%1], 16;" :: "r"(dst), "l"(src))
#define CP_COMMIT() asm volatile("cp.async.commit_group;" ::: "memory")
#define CP_WAIT0()  asm volatile("cp.async.wait_group 0;" ::: "memory")
#define CP_WAIT1()  asm volatile("cp.async.wait_group 1;" ::: "memory")

// mma.sync m16n8k16 bf16 -> fp32 (legacy HMMA path, valid on compute_103)
#define MMA16816(d, a, b) \
    asm volatile( \
        "mma.sync.aligned.m16n8k16.row.col.f32.bf16.bf16.f32 " \
        "{%0,%1,%2,%3}, {%4,%5,%6,%7}, {%8,%9}, {%0,%1,%2,%3};" \
        : "+f"((d)[0]), "+f"((d)[1]), "+f"((d)[2]), "+f"((d)[3]) \
        : "r"((a)[0]), "r"((a)[1]), "r"((a)[2]), "r"((a)[3]), \
          "r"((b)[0]), "r"((b)[1]))

// ---------------- RoPE table ----------------
__global__ void rope_table_kernel() {
    int idx = blockIdx.x * blockDim.x + threadIdx.x;
    if (idx >= L_ * 32) return;
    int l = idx >> 5;
    int j = idx & 31;
    float inv = powf(10000.0f, -(float)j / 32.0f);
    float ang = (float)l * inv;
    float s, c;
    sincosf(ang, &s, &c);
    g_cos[idx] = c;
    g_sin[idx] = s;
}

// ---------------- hi/lo bf16 split for weights ----------------
__global__ void split_kernel(const float* __restrict__ x,
                             __nv_bfloat16* __restrict__ hi,
                             __nv_bfloat16* __restrict__ lo) {
    int i = (blockIdx.x * 256 + threadIdx.x) * 4;
    float4 v = *(const float4*)&x[i];
    float vv[4] = {v.x, v.y, v.z, v.w};
    union { __nv_bfloat16 h[4]; uint2 u; } a, b;
    #pragma unroll
    for (int j = 0; j < 4; j++) {
        __nv_bfloat16 hb = __float2bfloat16(vv[j]);
        a.h[j] = hb;
        b.h[j] = __float2bfloat16(vv[j] - __bfloat162float(hb));
    }
    *(uint2*)&hi[i] = a.u;
    *(uint2*)&lo[i] = b.u;
}

// ---------------- LN1 -> bf16 hi/lo ----------------
__global__ void ln1_kernel(const float* __restrict__ x,
                           const float* __restrict__ w,
                           const float* __restrict__ b) {
    int n = blockIdx.x;
    const float* xr = x + (size_t)n * D_;
    int t = threadIdx.x;
    float4 v = *(const float4*)&xr[t * 4];
    float s  = v.x + v.y + v.z + v.w;
    float s2 = v.x*v.x + v.y*v.y + v.z*v.z + v.w*v.w;
    #pragma unroll
    for (int o = 16; o >= 1; o >>= 1) {
        s  += __shfl_xor_sync(0xffffffffu, s,  o);
        s2 += __shfl_xor_sync(0xffffffffu, s2, o);
    }
    __shared__ float red[2][8];
    int lane = t & 31, wp = t >> 5;
    if (lane == 0) { red[0][wp] = s; red[1][wp] = s2; }
    __syncthreads();
    __shared__ float stat[2];
    if (t == 0) {
        float a = 0.f, c = 0.f;
        #pragma unroll
        for (int i = 0; i < 8; i++) { a += red[0][i]; c += red[1][i]; }
        float mu  = a * (1.0f / D_);
        float var = c * (1.0f / D_) - mu * mu;
        stat[0] = mu;
        stat[1] = rsqrtf(var + EPS);
    }
    __syncthreads();
    float mu = stat[0], rs = stat[1];
    float4 wv = *(const float4*)&w[t * 4];
    float4 bv = *(const float4*)&b[t * 4];
    float oo[4];
    oo[0] = (v.x - mu) * rs * wv.x + bv.x;
    oo[1] = (v.y - mu) * rs * wv.y + bv.y;
    oo[2] = (v.z - mu) * rs * wv.z + bv.z;
    oo[3] = (v.w - mu) * rs * wv.w + bv.w;
    union { __nv_bfloat16 h[4]; uint2 u; } a, bb;
    #pragma unroll
    for (int j = 0; j < 4; j++) {
        __nv_bfloat16 hb = __float2bfloat16(oo[j]);
        a.h[j]  = hb;
        bb.h[j] = __float2bfloat16(oo[j] - __bfloat162float(hb));
    }
    size_t oidx = (size_t)n * D_ + t * 4;
    *(uint2*)&g_hh[oidx] = a.u;
    *(uint2*)&g_hl[oidx] = bb.u;
}

// ============ warp-MMA bf16 split-3 GEMM (R5-proven schedule) ============
__global__ __launch_bounds__(256) void gemm_mma(
    const __nv_bfloat16* __restrict__ Ah, const __nv_bfloat16* __restrict__ Al,
    const __nv_bfloat16* __restrict__ Bh, const __nv_bfloat16* __restrict__ Bl,
    float* __restrict__ C, int M, int N, int K)
{
    __shared__ __nv_bfloat16 sA[2][2][128 * 16];
    __shared__ __nv_bfloat16 sB[2][2][128 * 16];

    int tid = threadIdx.x;
    int warp = tid >> 5, lane = tid & 31;
    int m0 = blockIdx.y * 128, n0 = blockIdx.x * 128;
    int wm = (warp & 1) * 64, wn = (warp >> 1) * 32;

    int lrow = tid >> 1;
    int lch  = (tid & 1) * 8;

    const __nv_bfloat16* gA[2] = {Ah + (size_t)(m0 + lrow) * K + lch,
                                  Al + (size_t)(m0 + lrow) * K + lch};
    const __nv_bfloat16* gB[2] = {Bh + (size_t)(n0 + lrow) * K + lch,
                                  Bl + (size_t)(n0 + lrow) * K + lch};

    float d[4][4][4];
    #pragma unroll
    for (int mi = 0; mi < 4; mi++)
        #pragma unroll
        for (int ni = 0; ni < 4; ni++)
            #pragma unroll
            for (int r = 0; r < 4; r++) d[mi][ni][r] = 0.f;

    const int nstep = K >> 4;

    #pragma unroll
    for (int s = 0; s < 2; s++) {
        int st = s & 1;
        #pragma unroll
        for (int sp = 0; sp < 2; sp++) {
            CP_ASYNC16(smem_u32(&sA[st][sp][lrow * 16 + lch]), gA[sp] + s * 16);
            CP_ASYNC16(smem_u32(&sB[st][sp][lrow * 16 + lch]), gB[sp] + s * 16);
        }
        CP_COMMIT();
    }

    int ar = wm + (lane >> 2);
    int ac = (lane & 3) * 2;
    int br = wn + (lane >> 2);
    int bc = (lane & 3) * 2;

    for (int s = 0; s < nstep; s++) {
        int st = s & 1;
        if (s == nstep - 1) { CP_WAIT0(); } else { CP_WAIT1(); }
        __syncthreads();

        const __nv_bfloat16* pAh = &sA[st][0][0];
        const __nv_bfloat16* pAl = &sA[st][1][0];
        const __nv_bfloat16* pBh = &sB[st][0][0];
        const __nv_bfloat16* pBl = &sB[st][1][0];

        uint32_t ah[4][4], al[4][4], bh[4][2], bl[4][2];
        #pragma unroll
        for (int mi = 0; mi < 4; mi++) {
            int r0 = (ar + mi * 16) * 16 + ac;
            int r1 = r0 + 8 * 16;
            ah[mi][0] = *(const uint32_t*)(pAh + r0);
            ah[mi][1] = *(const uint32_t*)(pAh + r1);
            ah[mi][2] = *(const uint32_t*)(pAh + r0 + 8);
            ah[mi][3] = *(const uint32_t*)(pAh + r1 + 8);
            al[mi][0] = *(const uint32_t*)(pAl + r0);
            al[mi][1] = *(const uint32_t*)(pAl + r1);
            al[mi][2] = *(const uint32_t*)(pAl + r0 + 8);
            al[mi][3] = *(const uint32_t*)(pAl + r1 + 8);
        }
        #pragma unroll
        for (int ni = 0; ni < 4; ni++) {
            int c0 = (br + ni * 8) * 16 + bc;
            bh[ni][0] = *(const uint32_t*)(pBh + c0);
            bh[ni][1] = *(const uint32_t*)(pBh + c0 + 8);
            bl[ni][0] = *(const uint32_t*)(pBl + c0);
            bl[ni][1] = *(const uint32_t*)(pBl + c0 + 8);
        }

        #pragma unroll
        for (int mi = 0; mi < 4; mi++)
            #pragma unroll
            for (int ni = 0; ni < 4; ni++) {
                MMA16816(d[mi][ni], ah[mi], bh[ni]);
                MMA16816(d[mi][ni], ah[mi], bl[ni]);
                MMA16816(d[mi][ni], al[mi], bh[ni]);
            }

        __syncthreads();
        if (s + 2 < nstep) {
            #pragma unroll
            for (int sp = 0; sp < 2; sp++) {
                CP_ASYNC16(smem_u32(&sA[st][sp][lrow * 16 + lch]),
                           gA[sp] + (s + 2) * 16);
                CP_ASYNC16(smem_u32(&sB[st][sp][lrow * 16 + lch]),
                           gB[sp] + (s + 2) * 16);
            }
            CP_COMMIT();
        }
    }

    #pragma unroll
    for (int mi = 0; mi < 4; mi++) {
        int r = m0 + wm + mi * 16 + (lane >> 2);
        #pragma unroll
        for (int ni = 0; ni < 4; ni++) {
            int c = n0 + wn + ni * 8 + (lane & 3) * 2;
            *(float2*)&C[(size_t)r * N + c] = make_float2(d[mi][ni][0], d[mi][ni][1]);
            *(float2*)&C[(size_t)(r + 8) * N + c] = make_float2(d[mi][ni][2], d[mi][ni][3]);
        }
    }
}

// ---------------- fused QK-LN + RoPE -> bf16 hi/lo [BH,L,DH] ----------------
__global__ void qk_rope_kernel(const float* __restrict__ qw,
                               const float* __restrict__ kw) {
    int n = blockIdx.x;
    int b = n >> 11;
    int l = n & 2047;
    const float* q = g_qkv + (size_t)n * D3;
    const float* k = q + D_;
    int t = threadIdx.x;

    float4 qv = *(const float4*)&q[t * 4];
    float4 kv = *(const float4*)&k[t * 4];
    float qs  = qv.x + qv.y + qv.z + qv.w;
    float qs2 = qv.x*qv.x + qv.y*qv.y + qv.z*qv.z + qv.w*qv.w;
    float ks  = kv.x + kv.y + kv.z + kv.w;
    float ks2 = kv.x*kv.x + kv.y*kv.y + kv.z*kv.z + kv.w*kv.w;
    #pragma unroll
    for (int o = 16; o >= 1; o >>= 1) {
        qs  += __shfl_xor_sync(0xffffffffu, qs,  o);
        qs2 += __shfl_xor_sync(0xffffffffu, qs2, o);
        ks  += __shfl_xor_sync(0xffffffffu, ks,  o);
        ks2 += __shfl_xor_sync(0xffffffffu, ks2, o);
    }
    __shared__ float red[4][8];
    __shared__ float stat[4];
    __shared__ float qn[D_], kn[D_];
    int lane = t & 31, wp = t >> 5;
    if (lane == 0) { red[0][wp]=qs; red[1][wp]=qs2; red[2][wp]=ks; red[3][wp]=ks2; }
    __syncthreads();
    if (t == 0) {
        float a=0,c=0,e=0,f=0;
        #pragma unroll
        for (int i=0;i<8;i++){a+=red[0][i];c+=red[1][i];e+=red[2][i];f+=red[3][i];}
        float qmu=a*(1.f/D_), qvr=c*(1.f/D_)-qmu*qmu;
        float kmu=e*(1.f/D_), kvr=f*(1.f/D_)-kmu*kmu;
        stat[0]=qmu; stat[1]=rsqrtf(qvr+EPS);
        stat[2]=kmu; stat[3]=rsqrtf(kvr+EPS);
    }
    __syncthreads();
    float qmu=stat[0], qrs=stat[1], kmu=stat[2], krs=stat[3];
    float4 qwv = *(const float4*)&qw[t*4];
    float4 kwv = *(const float4*)&kw[t*4];
    qn[t*4+0]=(qv.x-qmu)*qrs*qwv.x; qn[t*4+1]=(qv.y-qmu)*qrs*qwv.y;
    qn[t*4+2]=(qv.z-qmu)*qrs*qwv.z; qn[t*4+3]=(qv.w-qmu)*qrs*qwv.w;
    kn[t*4+0]=(kv.x-kmu)*krs*kwv.x; kn[t*4+1]=(kv.y-kmu)*krs*kwv.y;
    kn[t*4+2]=(kv.z-kmu)*krs*kwv.z; kn[t*4+3]=(kv.w-kmu)*krs*kwv.w;
    __syncthreads();

    int d0 = t * 4;
    int hh = d0 >> 6;
    int j0 = d0 & 63;
    float qo[4], ko[4];
    #pragma unroll
    for (int ii = 0; ii < 4; ii++) {
        int d = d0 + ii;
        int j = j0 + ii;
        int f = j & 31;
        float c = g_cos[l * 32 + f];
        float s = g_sin[l * 32 + f];
        if (j < 32) {
            qo[ii] = qn[d] * c - qn[d + 32] * s;
            ko[ii] = kn[d] * c - kn[d + 32] * s;
        } else {
            qo[ii] = qn[d] * c + qn[d - 32] * s;
            ko[ii] = kn[d] * c + kn[d - 32] * s;
        }
        qo[ii] *= 0.125f;   // fold softmax scale into q
    }
    size_t oidx = (((size_t)(b * H_ + hh)) * L_ + l) * DH + j0;
    union { __nv_bfloat16 h[4]; uint2 u; } uqh, uql, ukh, ukl;
    #pragma unroll
    for (int ii = 0; ii < 4; ii++) {
        __nv_bfloat16 hb = __float2bfloat16(qo[ii]);
        uqh.h[ii] = hb;
        uql.h[ii] = __float2bfloat16(qo[ii] - __bfloat162float(hb));
        __nv_bfloat16 kb = __float2bfloat16(ko[ii]);
        ukh.h[ii] = kb;
        ukl.h[ii] = __float2bfloat16(ko[ii] - __bfloat162float(kb));
    }
    *(uint2*)&g_qh[oidx] = uqh.u;
    *(uint2*)&g_ql[oidx] = uql.u;
    *(uint2*)&g_kh[oidx] = ukh.u;
    *(uint2*)&g_kl[oidx] = ukl.u;
}

// ---------------- V transpose: g_qkv v-part -> [BH,DH,L] bf16 hi/lo ----------------
__global__ void vt_kernel() {
    __shared__ float tile[64][33];
    int bh = blockIdx.y;
    int b = bh >> 4, h = bh & 15;
    int l0 = blockIdx.x * 32;
    int tx = threadIdx.x & 31, ty = threadIdx.x >> 5;   // 256 threads

    #pragma unroll
    for (int i = 0; i < 4; i++) {
        int l = l0 + ty + i * 8;
        const float* row = g_qkv + (size_t)(b * L_ + l) * D3 + 2 * D_ + h * DH;
        tile[tx][ty + i * 8]      = row[tx];
        tile[tx + 32][ty + i * 8] = row[tx + 32];
    }
    __syncthreads();
    #pragma unroll
    for (int i = 0; i < 8; i++) {
        int d = ty + i * 8;
        float v = tile[d][tx];
        __nv_bfloat16 hb = __float2bfloat16(v);
        __nv_bfloat16 lb = __float2bfloat16(v - __bfloat162float(hb));
        size_t o = (size_t)(bh * DH + d) * L_ + l0 + tx;
        g_vth[o] = hb;
        g_vtl[o] = lb;
    }
}

// ---------------- flash attention on mma.sync (bf16 split-3) ----------------
// Block-diagonal mask: seq_id sorted -> valid k-tiles form a contiguous range.
#define KPAD 72
#define AT_SM_QH 0
#define AT_SM_QL 9216
#define AT_SM_KV 18432
#define AT_SM_TILE 9216
#define AT_SM_BUF 36864
#define AT_SM_SK (18432 + 2 * 36864)
#define ATT2_SMEM (AT_SM_SK + 512)

__global__ __launch_bounds__(128) void attn_mma(const int* __restrict__ seq_id) {
    extern __shared__ char sm[];
    const uint32_t sbase = smem_u32(sm);
    int tid = threadIdx.x, lane = tid & 31, w = tid >> 5;
    int qt = blockIdx.x, h = blockIdx.y, b = blockIdx.z;
    int bh = b * H_ + h;
    int row0 = qt * 64;

    const __nv_bfloat16* gQh = g_qh + ((size_t)bh * L_ + row0) * DH;
    const __nv_bfloat16* gQl = g_ql + ((size_t)bh * L_ + row0) * DH;
    const __nv_bfloat16* gKh = g_kh + (size_t)bh * L_ * DH;
    const __nv_bfloat16* gKl = g_kl + (size_t)bh * L_ * DH;
    const __nv_bfloat16* gVh = g_vth + (size_t)bh * DH * L_;
    const __nv_bfloat16* gVl = g_vtl + (size_t)bh * DH * L_;

    // ---- valid k-tile range (contiguous because seq_id is sorted) ----
    int q_lo = seq_id[b * L_ + row0];
    int q_hi = seq_id[b * L_ + row0 + 63];
    unsigned vmask;
    {
        int klo = seq_id[b * L_ + lane * 64];
        int khi = seq_id[b * L_ + lane * 64 + 63];
        bool ok = (khi >= q_lo) && (klo <= q_hi);
        vmask = __ballot_sync(0xffffffffu, ok);
    }
    int tlo = __ffs(vmask) - 1;
    int thi = 31 - __clz(vmask);

    int lrow = tid >> 1;          // 0..63
    int cb0  = (tid & 1) * 4;     // chunk base (16B chunks)

    // ---- prologue: Q tiles ----
    #pragma unroll
    for (int c = 0; c < 4; c++) {
        int ch = cb0 + c;
        uint32_t so = (uint32_t)(lrow * KPAD + ch * 8) * 2;
        CP_ASYNC16(sbase + AT_SM_QH + so, gQh + lrow * DH + ch * 8);
        CP_ASYNC16(sbase + AT_SM_QL + so, gQl + lrow * DH + ch * 8);
    }
    CP_COMMIT();
    // ---- K/V tile tlo ----
    {
        int col0 = tlo * 64;
        uint32_t dst = sbase + AT_SM_KV;
        #pragma unroll
        for (int c = 0; c < 4; c++) {
            int ch = cb0 + c;
            uint32_t so = (uint32_t)(lrow * KPAD + ch * 8) * 2;
            CP_ASYNC16(dst + so,                  gKh + (size_t)(col0 + lrow) * DH + ch * 8);
            CP_ASYNC16(dst + AT_SM_TILE + so,     gKl + (size_t)(col0 + lrow) * DH + ch * 8);
            CP_ASYNC16(dst + 2 * AT_SM_TILE + so, gVh + (size_t)lrow * L_ + col0 + ch * 8);
            CP_ASYNC16(dst + 3 * AT_SM_TILE + so, gVl + (size_t)lrow * L_ + col0 + ch * 8);
        }
    }
    CP_COMMIT();
    if (tid < 64) ((int*)(sm + AT_SM_SK))[tid] = seq_id[b * L_ + tlo * 64 + tid];
    int sq0 = seq_id[b * L_ + row0 + w * 16 + (lane >> 2)];
    int sq1 = seq_id[b * L_ + row0 + w * 16 + (lane >> 2) + 8];

    CP_WAIT1();
    __syncthreads();

    // ---- extract Q fragments (held for whole kernel) ----
    uint32_t qfh[4][4], qfl[4][4];
    {
        const __nv_bfloat16* sQh = (const __nv_bfloat16*)(sm + AT_SM_QH);
        const __nv_bfloat16* sQl = (const __nv_bfloat16*)(sm + AT_SM_QL);
        #pragma unroll
        for (int s = 0; s < 4; s++) {
            int base = (w * 16 + (lane >> 2)) * KPAD + s * 16 + (lane & 3) * 2;
            qfh[s][0] = *(const uint32_t*)(sQh + base);
            qfh[s][1] = *(const uint32_t*)(sQh + base + 8 * KPAD);
            qfh[s][2] = *(const uint32_t*)(sQh + base + 8);
            qfh[s][3] = *(const uint32_t*)(sQh + base + 8 * KPAD + 8);
            qfl[s][0] = *(const uint32_t*)(sQl + base);
            qfl[s][1] = *(const uint32_t*)(sQl + base + 8 * KPAD);
            qfl[s][2] = *(const uint32_t*)(sQl + base + 8);
            qfl[s][3] = *(const uint32_t*)(sQl + base + 8 * KPAD + 8);
        }
    }

    float m0 = -1e30f, m1 = -1e30f, l0 = 0.f, l1 = 0.f;
    float pv[8][4];
    #pragma unroll
    for (int j = 0; j < 8; j++)
        #pragma unroll
        for (int r = 0; r < 4; r++) pv[j][r] = 0.f;

    for (int it = tlo; it <= thi; it++) {
        int buf = (it - tlo) & 1;
        CP_WAIT0();
        __syncthreads();

        // prefetch next tile into other buffer
        if (it + 1 <= thi) {
            int col0n = (it + 1) * 64;
            uint32_t dst = sbase + AT_SM_KV + (buf ^ 1) * AT_SM_BUF;
            #pragma unroll
            for (int c = 0; c < 4; c++) {
                int ch = cb0 + c;
                uint32_t so = (uint32_t)(lrow * KPAD + ch * 8) * 2;
                CP_ASYNC16(dst + so,                  gKh + (size_t)(col0n + lrow) * DH + ch * 8);
                CP_ASYNC16(dst + AT_SM_TILE + so,     gKl + (size_t)(col0n + lrow) * DH + ch * 8);
                CP_ASYNC16(dst + 2 * AT_SM_TILE + so, gVh + (size_t)lrow * L_ + col0n + ch * 8);
                CP_ASYNC16(dst + 3 * AT_SM_TILE + so, gVl + (size_t)lrow * L_ + col0n + ch * 8);
            }
            if (tid < 64)
                ((int*)(sm + AT_SM_SK))[(buf ^ 1) * 64 + tid] =
                    seq_id[b * L_ + col0n + tid];
        }
        CP_COMMIT();

        const __nv_bfloat16* sKh = (const __nv_bfloat16*)(sm + AT_SM_KV + buf * AT_SM_BUF);
        const __nv_bfloat16* sKl = sKh + 4608;
        const __nv_bfloat16* sVh = sKh + 9216;
        const __nv_bfloat16* sVl = sKh + 13824;
        const int* skp = (const int*)(sm + AT_SM_SK) + buf * 64;

        // ---- S = Q K^T (split-3) ----
        float sf[8][4];
        #pragma unroll
        for (int j = 0; j < 8; j++)
            #pragma unroll
            for (int r = 0; r < 4; r++) sf[j][r] = 0.f;
        #pragma unroll
        for (int s = 0; s < 4; s++) {
            #pragma unroll
            for (int j = 0; j < 8; j++) {
                int off = (j * 8 + (lane >> 2)) * KPAD + s * 16 + (lane & 3) * 2;
                uint32_t bhf[2] = {*(const uint32_t*)(sKh + off),
                                   *(const uint32_t*)(sKh + off + 8)};
                uint32_t blf[2] = {*(const uint32_t*)(sKl + off),
                                   *(const uint32_t*)(sKl + off + 8)};
                MMA16816(sf[j], qfh[s], bhf);
                MMA16816(sf[j], qfh[s], blf);
                MMA16816(sf[j], qfl[s], bhf);
            }
        }

        // ---- mask + online softmax (c-frag layout) ----
        int colb = (lane & 3) * 2;
        float nm0 = m0, nm1 = m1;
        #pragma unroll
        for (int j = 0; j < 8; j++) {
            int k0 = skp[8 * j + colb], k1 = skp[8 * j + colb + 1];
            sf[j][0] = (k0 == sq0) ? sf[j][0] : -2e30f;
            sf[j][1] = (k1 == sq0) ? sf[j][1] : -2e30f;
            sf[j][2] = (k0 == sq1) ? sf[j][2] : -2e30f;
            sf[j][3] = (k1 == sq1) ? sf[j][3] : -2e30f;
            nm0 = fmaxf(nm0, fmaxf(sf[j][0], sf[j][1]));
            nm1 = fmaxf(nm1, fmaxf(sf[j][2], sf[j][3]));
        }
        nm0 = fmaxf(nm0, __shfl_xor_sync(0xffffffffu, nm0, 1));
        nm0 = fmaxf(nm0, __shfl_xor_sync(0xffffffffu, nm0, 2));
        nm1 = fmaxf(nm1, __shfl_xor_sync(0xffffffffu, nm1, 1));
        nm1 = fmaxf(nm1, __shfl_xor_sync(0xffffffffu, nm1, 2));
        float a0 = __expf(m0 - nm0), a1 = __expf(m1 - nm1);
        m0 = nm0; m1 = nm1;

        float s0 = 0.f, s1 = 0.f;
        uint32_t ph[4][4], pl[4][4];
        #pragma unroll
        for (int j = 0; j < 8; j++) {
            float p0 = __expf(sf[j][0] - m0), p1 = __expf(sf[j][1] - m0);
            float p2 = __expf(sf[j][2] - m1), p3 = __expf(sf[j][3] - m1);
            s0 += p0 + p1; s1 += p2 + p3;
            __nv_bfloat162 h01 = __float22bfloat162_rn(make_float2(p0, p1));
            float2 f01 = __bfloat1622float2(h01);
            __nv_bfloat162 l01 = __float22bfloat162_rn(make_float2(p0 - f01.x, p1 - f01.y));
            __nv_bfloat162 h23 = __float22bfloat162_rn(make_float2(p2, p3));
            float2 f23 = __bfloat1622float2(h23);
            __nv_bfloat162 l23 = __float22bfloat162_rn(make_float2(p2 - f23.x, p3 - f23.y));
            int s_ = j >> 1;
            int o  = (j & 1) * 2;
            ph[s_][o]     = *(uint32_t*)&h01;
            ph[s_][o + 1] = *(uint32_t*)&h23;
            pl[s_][o]     = *(uint32_t*)&l01;
            pl[s_][o + 1] = *(uint32_t*)&l23;
        }
        s0 += __shfl_xor_sync(0xffffffffu, s0, 1);
        s0 += __shfl_xor_sync(0xffffffffu, s0, 2);
        s1 += __shfl_xor_sync(0xffffffffu, s1, 1);
        s1 += __shfl_xor_sync(0xffffffffu, s1, 2);
        l0 = l0 * a0 + s0;
        l1 = l1 * a1 + s1;
        #pragma unroll
        for (int j = 0; j < 8; j++) {
            pv[j][0] *= a0; pv[j][1] *= a0; pv[j][2] *= a1; pv[j][3] *= a1;
        }

        // ---- PV (split-3), B = Vt[dh][c] ----
        #pragma unroll
        for (int s = 0; s < 4; s++) {
            #pragma unroll
            for (int j = 0; j < 8; j++) {
                int off = (j * 8 + (lane >> 2)) * KPAD + s * 16 + (lane & 3) * 2;
                uint32_t bhf[2] = {*(const uint32_t*)(sVh + off),
                                   *(const uint32_t*)(sVh + off + 8)};
                uint32_t blf[2] = {*(const uint32_t*)(sVl + off),
                                   *(const uint32_t*)(sVl + off + 8)};
                MMA16816(pv[j], ph[s], bhf);
                MMA16816(pv[j], ph[s], blf);
                MMA16816(pv[j], pl[s], bhf);
            }
        }
    }

    // ---- epilogue: ctx / l -> bf16 hi/lo [B,L,H,DH] ----
    float inv0 = 1.0f / l0, inv1 = 1.0f / l1;
    int r0g = row0 + w * 16 + (lane >> 2);
    #pragma unroll
    for (int j = 0; j < 8; j++) {
        int c = 8 * j + (lane & 3) * 2;
        size_t o0 = (((size_t)b * L_ + r0g) * H_ + h) * DH + c;
        size_t o1 = (((size_t)b * L_ + r0g + 8) * H_ + h) * DH + c;
        float x0 = pv[j][0] * inv0, x1 = pv[j][1] * inv0;
        float y0 = pv[j][2] * inv1, y1 = pv[j][3] * inv1;
        __nv_bfloat162 hx = __float22bfloat162_rn(make_float2(x0, x1));
        float2 fx = __bfloat1622float2(hx);
        __nv_bfloat162 lx = __float22bfloat162_rn(make_float2(x0 - fx.x, x1 - fx.y));
        __nv_bfloat162 hy = __float22bfloat162_rn(make_float2(y0, y1));
        float2 fy = __bfloat1622float2(hy);
        __nv_bfloat162 ly = __float22bfloat162_rn(make_float2(y0 - fy.x, y1 - fy.y));
        *(uint32_t*)&g_ch[o0] = *(uint32_t*)&hx;
        *(uint32_t*)&g_cl[o0] = *(uint32_t*)&lx;
        *(uint32_t*)&g_ch[o1] = *(uint32_t*)&hy;
        *(uint32_t*)&g_cl[o1] = *(uint32_t*)&ly;
    }
}

// ---------------- launch ----------------
extern "C" void kernel_launch(void* const* d_in, const int* in_sizes, int n_in,
                              void* d_out, int out_size) {
    const float* x      = (const float*)d_in[0];
    const int*   seq_id = (const int*)  d_in[1];
    const float* ln1_w  = (const float*)d_in[2];
    const float* ln1_b  = (const float*)d_in[3];
    const float* w_qkv  = (const float*)d_in[4];
    const float* q_ln_w = (const float*)d_in[5];
    const float* k_ln_w = (const float*)d_in[6];
    const float* out_w  = (const float*)d_in[7];
    float* out = (float*)d_out;

    void *phh, *phl, *pwqh, *pwql, *powh, *powl, *pch, *pcl, *pqkv;
    cudaGetSymbolAddress(&phh,  g_hh);
    cudaGetSymbolAddress(&phl,  g_hl);
    cudaGetSymbolAddress(&pwqh, g_wqh);
    cudaGetSymbolAddress(&pwql, g_wql);
    cudaGetSymbolAddress(&powh, g_owh);
    cudaGetSymbolAddress(&powl, g_owl);
    cudaGetSymbolAddress(&pch,  g_ch);
    cudaGetSymbolAddress(&pcl,  g_cl);
    cudaGetSymbolAddress(&pqkv, g_qkv);

    cudaFuncSetAttribute(attn_mma, cudaFuncAttributeMaxDynamicSharedMemorySize,
                         ATT2_SMEM);

    rope_table_kernel<<<(L_ * 32 + 255) / 256, 256>>>();
    split_kernel<<<(D3 * D_) / 1024, 256>>>(w_qkv, (__nv_bfloat16*)pwqh,
                                            (__nv_bfloat16*)pwql);
    split_kernel<<<(D_ * D_) / 1024, 256>>>(out_w, (__nv_bfloat16*)powh,
                                            (__nv_bfloat16*)powl);
    ln1_kernel<<<NT, 256>>>(x, ln1_w, ln1_b);
    gemm_mma<<<dim3(D3 / 128, NT / 128), 256>>>(
        (const __nv_bfloat16*)phh, (const __nv_bfloat16*)phl,
        (const __nv_bfloat16*)pwqh, (const __nv_bfloat16*)pwql,
        (float*)pqkv, NT, D3, D_);
    qk_rope_kernel<<<NT, 256>>>(q_ln_w, k_ln_w);
    vt_kernel<<<dim3(L_ / 32, B_ * H_), 256>>>();
    attn_mma<<<dim3(L_ / 64, H_, B_), 128, ATT2_SMEM>>>(seq_id);
    gemm_mma<<<dim3(D_ / 128, NT / 128), 256>>>(
        (const __nv_bfloat16*)pch, (const __nv_bfloat16*)pcl,
        (const __nv_bfloat16*)powh, (const __nv_bfloat16*)powl,
        out, NT, D_, D_);
}

// round 9
// speedup vs baseline: 1.6434x; 1.0471x over previous
#include <cuda_runtime.h>
#include <cuda_bf16.h>
#include <cstdint>
#include <math.h>

// Problem constants
#define B_  2
#define L_  2048
#define NT  4096            // B*L tokens
#define D_  1024
#define H_  16
#define DH  64
#define D3  3072
#define EPS 1e-5f

// ---------------- scratch (device globals; no allocation) ----------------
__device__ __nv_bfloat16 g_hh[NT * D_];   // LN1 out hi
__device__ __nv_bfloat16 g_hl[NT * D_];   // LN1 out lo
__device__ __nv_bfloat16 g_wqh[D3 * D_];  // w_qkv hi
__device__ __nv_bfloat16 g_wql[D3 * D_];  // w_qkv lo
__device__ __nv_bfloat16 g_owh[D_ * D_];  // out_w hi
__device__ __nv_bfloat16 g_owl[D_ * D_];  // out_w lo
__device__ __nv_bfloat16 g_ch[NT * D_];   // ctx hi   [B,L,H,DH] == [NT,D]
__device__ __nv_bfloat16 g_cl[NT * D_];   // ctx lo
__device__ __nv_bfloat16 g_qh[NT * D_];   // q (scaled) hi  [BH,L,DH]
__device__ __nv_bfloat16 g_ql[NT * D_];
__device__ __nv_bfloat16 g_kh[NT * D_];   // k hi [BH,L,DH]
__device__ __nv_bfloat16 g_kl[NT * D_];
__device__ __nv_bfloat16 g_vth[NT * D_];  // v^T hi [BH,DH,L]
__device__ __nv_bfloat16 g_vtl[NT * D_];
__device__ float g_qkv[NT * D3];          // QKV gemm output [NT, 3D]
__device__ float g_cos[L_ * 32];
__device__ float g_sin[L_ * 32];

// ---------------- helpers ----------------
__device__ __forceinline__ uint32_t smem_u32(const void* p) {
    uint32_t a;
    asm("{ .reg .u64 t; cvta.to.shared.u64 t, %1; cvt.u32.u64 %0, t; }"
        : "=r"(a) : "l"(p));
    return a;
}
#define CP_ASYNC16(dst, src) \
    asm volatile("cp.async.cg.shared.global [%0], [%1], 16;" :: "r"(dst), "l"(src))
#define CP_COMMIT() asm volatile("cp.async.commit_group;" ::: "memory")
#define CP_WAIT0()  asm volatile("cp.async.wait_group 0;" ::: "memory")
#define CP_WAIT1()  asm volatile("cp.async.wait_group 1;" ::: "memory")

// mma.sync m16n8k16 bf16 -> fp32 (legacy HMMA path, valid on compute_103)
#define MMA16816(d, a, b) \
    asm volatile( \
        "mma.sync.aligned.m16n8k16.row.col.f32.bf16.bf16.f32 " \
        "{%0,%1,%2,%3}, {%4,%5,%6,%7}, {%8,%9}, {%0,%1,%2,%3};" \
        : "+f"((d)[0]), "+f"((d)[1]), "+f"((d)[2]), "+f"((d)[3]) \
        : "r"((a)[0]), "r"((a)[1]), "r"((a)[2]), "r"((a)[3]), \
          "r"((b)[0]), "r"((b)[1]))

// ---------------- RoPE table ----------------
__global__ void rope_table_kernel() {
    int idx = blockIdx.x * blockDim.x + threadIdx.x;
    if (idx >= L_ * 32) return;
    int l = idx >> 5;
    int j = idx & 31;
    float inv = powf(10000.0f, -(float)j / 32.0f);
    float ang = (float)l * inv;
    float s, c;
    sincosf(ang, &s, &c);
    g_cos[idx] = c;
    g_sin[idx] = s;
}

// ---------------- hi/lo bf16 split for weights ----------------
__global__ void split_kernel(const float* __restrict__ x,
                             __nv_bfloat16* __restrict__ hi,
                             __nv_bfloat16* __restrict__ lo) {
    int i = (blockIdx.x * 256 + threadIdx.x) * 4;
    float4 v = *(const float4*)&x[i];
    float vv[4] = {v.x, v.y, v.z, v.w};
    union { __nv_bfloat16 h[4]; uint2 u; } a, b;
    #pragma unroll
    for (int j = 0; j < 4; j++) {
        __nv_bfloat16 hb = __float2bfloat16(vv[j]);
        a.h[j] = hb;
        b.h[j] = __float2bfloat16(vv[j] - __bfloat162float(hb));
    }
    *(uint2*)&hi[i] = a.u;
    *(uint2*)&lo[i] = b.u;
}

// ---------------- LN1 -> bf16 hi/lo ----------------
__global__ void ln1_kernel(const float* __restrict__ x,
                           const float* __restrict__ w,
                           const float* __restrict__ b) {
    int n = blockIdx.x;
    const float* xr = x + (size_t)n * D_;
    int t = threadIdx.x;
    float4 v = *(const float4*)&xr[t * 4];
    float s  = v.x + v.y + v.z + v.w;
    float s2 = v.x*v.x + v.y*v.y + v.z*v.z + v.w*v.w;
    #pragma unroll
    for (int o = 16; o >= 1; o >>= 1) {
        s  += __shfl_xor_sync(0xffffffffu, s,  o);
        s2 += __shfl_xor_sync(0xffffffffu, s2, o);
    }
    __shared__ float red[2][8];
    int lane = t & 31, wp = t >> 5;
    if (lane == 0) { red[0][wp] = s; red[1][wp] = s2; }
    __syncthreads();
    __shared__ float stat[2];
    if (t == 0) {
        float a = 0.f, c = 0.f;
        #pragma unroll
        for (int i = 0; i < 8; i++) { a += red[0][i]; c += red[1][i]; }
        float mu  = a * (1.0f / D_);
        float var = c * (1.0f / D_) - mu * mu;
        stat[0] = mu;
        stat[1] = rsqrtf(var + EPS);
    }
    __syncthreads();
    float mu = stat[0], rs = stat[1];
    float4 wv = *(const float4*)&w[t * 4];
    float4 bv = *(const float4*)&b[t * 4];
    float oo[4];
    oo[0] = (v.x - mu) * rs * wv.x + bv.x;
    oo[1] = (v.y - mu) * rs * wv.y + bv.y;
    oo[2] = (v.z - mu) * rs * wv.z + bv.z;
    oo[3] = (v.w - mu) * rs * wv.w + bv.w;
    union { __nv_bfloat16 h[4]; uint2 u; } a, bb;
    #pragma unroll
    for (int j = 0; j < 4; j++) {
        __nv_bfloat16 hb = __float2bfloat16(oo[j]);
        a.h[j]  = hb;
        bb.h[j] = __float2bfloat16(oo[j] - __bfloat162float(hb));
    }
    size_t oidx = (size_t)n * D_ + t * 4;
    *(uint2*)&g_hh[oidx] = a.u;
    *(uint2*)&g_hl[oidx] = bb.u;
}

// ============ warp-MMA bf16 split-3 GEMM v3 ============
// CTA 128x128, 8 warps of 64x32. 3 stages x K32 chunks (two K16 sub-buffers,
// byte-identical layout to the proven R5 sub-buffer). ONE __syncthreads per
// 96 MMAs; prefetch c+2 lands in a stage disjoint from both live stages.
// Dynamic smem: A 48KB + B 48KB = 96KB.
#define GSUB   (128 * 16)                 // bf16 elems per sub-buffer
#define GSPL   (2 * GSUB)                 // elems per sub-pair (hi,lo)  (4096)
#define GSTG   (2 * GSPL)                 // elems per stage (2 subs)    (8192)
#define GMAT   (3 * GSTG)                 // elems per matrix (3 stages) (24576)
#define GEMM_SMEM_BYTES (2 * GMAT * 2)    // 98304 B

__global__ __launch_bounds__(256) void gemm_mma(
    const __nv_bfloat16* __restrict__ Ah, const __nv_bfloat16* __restrict__ Al,
    const __nv_bfloat16* __restrict__ Bh, const __nv_bfloat16* __restrict__ Bl,
    float* __restrict__ C, int M, int N, int K)
{
    extern __shared__ __nv_bfloat16 smg[];
    __nv_bfloat16* sA = smg;            // [3][2 subs][2 splits][128*16]
    __nv_bfloat16* sB = smg + GMAT;

    int tid = threadIdx.x;
    int warp = tid >> 5, lane = tid & 31;
    int m0 = blockIdx.y * 128, n0 = blockIdx.x * 128;
    int wm = (warp & 1) * 64, wn = (warp >> 1) * 32;

    int lrow = tid >> 1;
    int lch  = (tid & 1) * 8;
    uint32_t uA = smem_u32(sA), uB = smem_u32(sB);
    uint32_t dsto = (uint32_t)(lrow * 16 + lch) * 2;    // within a split buffer

    const __nv_bfloat16* gA[2] = {Ah + (size_t)(m0 + lrow) * K + lch,
                                  Al + (size_t)(m0 + lrow) * K + lch};
    const __nv_bfloat16* gB[2] = {Bh + (size_t)(n0 + lrow) * K + lch,
                                  Bl + (size_t)(n0 + lrow) * K + lch};

    float d[4][4][4];
    #pragma unroll
    for (int mi = 0; mi < 4; mi++)
        #pragma unroll
        for (int ni = 0; ni < 4; ni++)
            #pragma unroll
            for (int r = 0; r < 4; r++) d[mi][ni][r] = 0.f;

    const int nchunk = K >> 5;          // K32 chunks

    // prologue: chunks 0,1 -> stages 0,1
    #pragma unroll
    for (int c = 0; c < 2; c++) {
        #pragma unroll
        for (int sub = 0; sub < 2; sub++)
            #pragma unroll
            for (int sp = 0; sp < 2; sp++) {
                uint32_t so = (uint32_t)(c * GSTG + sub * GSPL + sp * GSUB) * 2 + dsto;
                CP_ASYNC16(uA + so, gA[sp] + c * 32 + sub * 16);
                CP_ASYNC16(uB + so, gB[sp] + c * 32 + sub * 16);
            }
        CP_COMMIT();
    }

    int ar = wm + (lane >> 2);
    int ac = (lane & 3) * 2;
    int br = wn + (lane >> 2);
    int bc = (lane & 3) * 2;

    for (int c = 0; c < nchunk; c++) {
        int st = c % 3;
        if (c == nchunk - 1) { CP_WAIT0(); } else { CP_WAIT1(); }
        __syncthreads();

        // prefetch chunk c+2 into stage (c+2)%3 (disjoint from stages c, c+1)
        if (c + 2 < nchunk) {
            int sn = (c + 2) % 3;
            #pragma unroll
            for (int sub = 0; sub < 2; sub++)
                #pragma unroll
                for (int sp = 0; sp < 2; sp++) {
                    uint32_t so = (uint32_t)(sn * GSTG + sub * GSPL + sp * GSUB) * 2 + dsto;
                    CP_ASYNC16(uA + so, gA[sp] + (c + 2) * 32 + sub * 16);
                    CP_ASYNC16(uB + so, gB[sp] + (c + 2) * 32 + sub * 16);
                }
        }
        CP_COMMIT();    // commit even when empty: uniform group counting

        #pragma unroll
        for (int sub = 0; sub < 2; sub++) {
            const __nv_bfloat16* pAh = sA + st * GSTG + sub * GSPL;
            const __nv_bfloat16* pAl = pAh + GSUB;
            const __nv_bfloat16* pBh = sB + st * GSTG + sub * GSPL;
            const __nv_bfloat16* pBl = pBh + GSUB;

            uint32_t ah[4][4], al[4][4], bh[4][2], bl[4][2];
            #pragma unroll
            for (int mi = 0; mi < 4; mi++) {
                int r0 = (ar + mi * 16) * 16 + ac;
                int r1 = r0 + 8 * 16;
                ah[mi][0] = *(const uint32_t*)(pAh + r0);
                ah[mi][1] = *(const uint32_t*)(pAh + r1);
                ah[mi][2] = *(const uint32_t*)(pAh + r0 + 8);
                ah[mi][3] = *(const uint32_t*)(pAh + r1 + 8);
                al[mi][0] = *(const uint32_t*)(pAl + r0);
                al[mi][1] = *(const uint32_t*)(pAl + r1);
                al[mi][2] = *(const uint32_t*)(pAl + r0 + 8);
                al[mi][3] = *(const uint32_t*)(pAl + r1 + 8);
            }
            #pragma unroll
            for (int ni = 0; ni < 4; ni++) {
                int c0 = (br + ni * 8) * 16 + bc;
                bh[ni][0] = *(const uint32_t*)(pBh + c0);
                bh[ni][1] = *(const uint32_t*)(pBh + c0 + 8);
                bl[ni][0] = *(const uint32_t*)(pBl + c0);
                bl[ni][1] = *(const uint32_t*)(pBl + c0 + 8);
            }

            #pragma unroll
            for (int mi = 0; mi < 4; mi++)
                #pragma unroll
                for (int ni = 0; ni < 4; ni++) {
                    MMA16816(d[mi][ni], ah[mi], bh[ni]);
                    MMA16816(d[mi][ni], ah[mi], bl[ni]);
                    MMA16816(d[mi][ni], al[mi], bh[ni]);
                }
        }
    }

    #pragma unroll
    for (int mi = 0; mi < 4; mi++) {
        int r = m0 + wm + mi * 16 + (lane >> 2);
        #pragma unroll
        for (int ni = 0; ni < 4; ni++) {
            int c = n0 + wn + ni * 8 + (lane & 3) * 2;
            *(float2*)&C[(size_t)r * N + c] = make_float2(d[mi][ni][0], d[mi][ni][1]);
            *(float2*)&C[(size_t)(r + 8) * N + c] = make_float2(d[mi][ni][2], d[mi][ni][3]);
        }
    }
}

// ---------------- fused QK-LN + RoPE -> bf16 hi/lo [BH,L,DH] ----------------
__global__ void qk_rope_kernel(const float* __restrict__ qw,
                               const float* __restrict__ kw) {
    int n = blockIdx.x;
    int b = n >> 11;
    int l = n & 2047;
    const float* q = g_qkv + (size_t)n * D3;
    const float* k = q + D_;
    int t = threadIdx.x;

    float4 qv = *(const float4*)&q[t * 4];
    float4 kv = *(const float4*)&k[t * 4];
    float qs  = qv.x + qv.y + qv.z + qv.w;
    float qs2 = qv.x*qv.x + qv.y*qv.y + qv.z*qv.z + qv.w*qv.w;
    float ks  = kv.x + kv.y + kv.z + kv.w;
    float ks2 = kv.x*kv.x + kv.y*kv.y + kv.z*kv.z + kv.w*kv.w;
    #pragma unroll
    for (int o = 16; o >= 1; o >>= 1) {
        qs  += __shfl_xor_sync(0xffffffffu, qs,  o);
        qs2 += __shfl_xor_sync(0xffffffffu, qs2, o);
        ks  += __shfl_xor_sync(0xffffffffu, ks,  o);
        ks2 += __shfl_xor_sync(0xffffffffu, ks2, o);
    }
    __shared__ float red[4][8];
    __shared__ float stat[4];
    __shared__ float qn[D_], kn[D_];
    int lane = t & 31, wp = t >> 5;
    if (lane == 0) { red[0][wp]=qs; red[1][wp]=qs2; red[2][wp]=ks; red[3][wp]=ks2; }
    __syncthreads();
    if (t == 0) {
        float a=0,c=0,e=0,f=0;
        #pragma unroll
        for (int i=0;i<8;i++){a+=red[0][i];c+=red[1][i];e+=red[2][i];f+=red[3][i];}
        float qmu=a*(1.f/D_), qvr=c*(1.f/D_)-qmu*qmu;
        float kmu=e*(1.f/D_), kvr=f*(1.f/D_)-kmu*kmu;
        stat[0]=qmu; stat[1]=rsqrtf(qvr+EPS);
        stat[2]=kmu; stat[3]=rsqrtf(kvr+EPS);
    }
    __syncthreads();
    float qmu=stat[0], qrs=stat[1], kmu=stat[2], krs=stat[3];
    float4 qwv = *(const float4*)&qw[t*4];
    float4 kwv = *(const float4*)&kw[t*4];
    qn[t*4+0]=(qv.x-qmu)*qrs*qwv.x; qn[t*4+1]=(qv.y-qmu)*qrs*qwv.y;
    qn[t*4+2]=(qv.z-qmu)*qrs*qwv.z; qn[t*4+3]=(qv.w-qmu)*qrs*qwv.w;
    kn[t*4+0]=(kv.x-kmu)*krs*kwv.x; kn[t*4+1]=(kv.y-kmu)*krs*kwv.y;
    kn[t*4+2]=(kv.z-kmu)*krs*kwv.z; kn[t*4+3]=(kv.w-kmu)*krs*kwv.w;
    __syncthreads();

    int d0 = t * 4;
    int hh = d0 >> 6;
    int j0 = d0 & 63;
    float qo[4], ko[4];
    #pragma unroll
    for (int ii = 0; ii < 4; ii++) {
        int d = d0 + ii;
        int j = j0 + ii;
        int f = j & 31;
        float c = g_cos[l * 32 + f];
        float s = g_sin[l * 32 + f];
        if (j < 32) {
            qo[ii] = qn[d] * c - qn[d + 32] * s;
            ko[ii] = kn[d] * c - kn[d + 32] * s;
        } else {
            qo[ii] = qn[d] * c + qn[d - 32] * s;
            ko[ii] = kn[d] * c + kn[d - 32] * s;
        }
        qo[ii] *= 0.125f;   // fold softmax scale into q
    }
    size_t oidx = (((size_t)(b * H_ + hh)) * L_ + l) * DH + j0;
    union { __nv_bfloat16 h[4]; uint2 u; } uqh, uql, ukh, ukl;
    #pragma unroll
    for (int ii = 0; ii < 4; ii++) {
        __nv_bfloat16 hb = __float2bfloat16(qo[ii]);
        uqh.h[ii] = hb;
        uql.h[ii] = __float2bfloat16(qo[ii] - __bfloat162float(hb));
        __nv_bfloat16 kb = __float2bfloat16(ko[ii]);
        ukh.h[ii] = kb;
        ukl.h[ii] = __float2bfloat16(ko[ii] - __bfloat162float(kb));
    }
    *(uint2*)&g_qh[oidx] = uqh.u;
    *(uint2*)&g_ql[oidx] = uql.u;
    *(uint2*)&g_kh[oidx] = ukh.u;
    *(uint2*)&g_kl[oidx] = ukl.u;
}

// ---------------- V transpose: g_qkv v-part -> [BH,DH,L] bf16 hi/lo ----------------
__global__ void vt_kernel() {
    __shared__ float tile[64][33];
    int bh = blockIdx.y;
    int b = bh >> 4, h = bh & 15;
    int l0 = blockIdx.x * 32;
    int tx = threadIdx.x & 31, ty = threadIdx.x >> 5;   // 256 threads

    #pragma unroll
    for (int i = 0; i < 4; i++) {
        int l = l0 + ty + i * 8;
        const float* row = g_qkv + (size_t)(b * L_ + l) * D3 + 2 * D_ + h * DH;
        tile[tx][ty + i * 8]      = row[tx];
        tile[tx + 32][ty + i * 8] = row[tx + 32];
    }
    __syncthreads();
    #pragma unroll
    for (int i = 0; i < 8; i++) {
        int d = ty + i * 8;
        float v = tile[d][tx];
        __nv_bfloat16 hb = __float2bfloat16(v);
        __nv_bfloat16 lb = __float2bfloat16(v - __bfloat162float(hb));
        size_t o = (size_t)(bh * DH + d) * L_ + l0 + tx;
        g_vth[o] = hb;
        g_vtl[o] = lb;
    }
}

// ---------------- flash attention on mma.sync (bf16 split-3) ----------------
// Block-diagonal mask: seq_id sorted -> valid k-tiles form a contiguous range.
#define KPAD 72
#define AT_SM_QH 0
#define AT_SM_QL 9216
#define AT_SM_KV 18432
#define AT_SM_TILE 9216
#define AT_SM_BUF 36864
#define AT_SM_SK (18432 + 2 * 36864)
#define ATT2_SMEM (AT_SM_SK + 512)

__global__ __launch_bounds__(128) void attn_mma(const int* __restrict__ seq_id) {
    extern __shared__ char sm[];
    const uint32_t sbase = smem_u32(sm);
    int tid = threadIdx.x, lane = tid & 31, w = tid >> 5;
    int qt = blockIdx.x, h = blockIdx.y, b = blockIdx.z;
    int bh = b * H_ + h;
    int row0 = qt * 64;

    const __nv_bfloat16* gQh = g_qh + ((size_t)bh * L_ + row0) * DH;
    const __nv_bfloat16* gQl = g_ql + ((size_t)bh * L_ + row0) * DH;
    const __nv_bfloat16* gKh = g_kh + (size_t)bh * L_ * DH;
    const __nv_bfloat16* gKl = g_kl + (size_t)bh * L_ * DH;
    const __nv_bfloat16* gVh = g_vth + (size_t)bh * DH * L_;
    const __nv_bfloat16* gVl = g_vtl + (size_t)bh * DH * L_;

    // ---- valid k-tile range (contiguous because seq_id is sorted) ----
    int q_lo = seq_id[b * L_ + row0];
    int q_hi = seq_id[b * L_ + row0 + 63];
    unsigned vmask;
    {
        int klo = seq_id[b * L_ + lane * 64];
        int khi = seq_id[b * L_ + lane * 64 + 63];
        bool ok = (khi >= q_lo) && (klo <= q_hi);
        vmask = __ballot_sync(0xffffffffu, ok);
    }
    int tlo = __ffs(vmask) - 1;
    int thi = 31 - __clz(vmask);

    int lrow = tid >> 1;          // 0..63
    int cb0  = (tid & 1) * 4;     // chunk base (16B chunks)

    // ---- prologue: Q tiles ----
    #pragma unroll
    for (int c = 0; c < 4; c++) {
        int ch = cb0 + c;
        uint32_t so = (uint32_t)(lrow * KPAD + ch * 8) * 2;
        CP_ASYNC16(sbase + AT_SM_QH + so, gQh + lrow * DH + ch * 8);
        CP_ASYNC16(sbase + AT_SM_QL + so, gQl + lrow * DH + ch * 8);
    }
    CP_COMMIT();
    // ---- K/V tile tlo ----
    {
        int col0 = tlo * 64;
        uint32_t dst = sbase + AT_SM_KV;
        #pragma unroll
        for (int c = 0; c < 4; c++) {
            int ch = cb0 + c;
            uint32_t so = (uint32_t)(lrow * KPAD + ch * 8) * 2;
            CP_ASYNC16(dst + so,                  gKh + (size_t)(col0 + lrow) * DH + ch * 8);
            CP_ASYNC16(dst + AT_SM_TILE + so,     gKl + (size_t)(col0 + lrow) * DH + ch * 8);
            CP_ASYNC16(dst + 2 * AT_SM_TILE + so, gVh + (size_t)lrow * L_ + col0 + ch * 8);
            CP_ASYNC16(dst + 3 * AT_SM_TILE + so, gVl + (size_t)lrow * L_ + col0 + ch * 8);
        }
    }
    CP_COMMIT();
    if (tid < 64) ((int*)(sm + AT_SM_SK))[tid] = seq_id[b * L_ + tlo * 64 + tid];
    int sq0 = seq_id[b * L_ + row0 + w * 16 + (lane >> 2)];
    int sq1 = seq_id[b * L_ + row0 + w * 16 + (lane >> 2) + 8];

    CP_WAIT1();
    __syncthreads();

    // ---- extract Q fragments (held for whole kernel) ----
    uint32_t qfh[4][4], qfl[4][4];
    {
        const __nv_bfloat16* sQh = (const __nv_bfloat16*)(sm + AT_SM_QH);
        const __nv_bfloat16* sQl = (const __nv_bfloat16*)(sm + AT_SM_QL);
        #pragma unroll
        for (int s = 0; s < 4; s++) {
            int base = (w * 16 + (lane >> 2)) * KPAD + s * 16 + (lane & 3) * 2;
            qfh[s][0] = *(const uint32_t*)(sQh + base);
            qfh[s][1] = *(const uint32_t*)(sQh + base + 8 * KPAD);
            qfh[s][2] = *(const uint32_t*)(sQh + base + 8);
            qfh[s][3] = *(const uint32_t*)(sQh + base + 8 * KPAD + 8);
            qfl[s][0] = *(const uint32_t*)(sQl + base);
            qfl[s][1] = *(const uint32_t*)(sQl + base + 8 * KPAD);
            qfl[s][2] = *(const uint32_t*)(sQl + base + 8);
            qfl[s][3] = *(const uint32_t*)(sQl + base + 8 * KPAD + 8);
        }
    }

    float m0 = -1e30f, m1 = -1e30f, l0 = 0.f, l1 = 0.f;
    float pv[8][4];
    #pragma unroll
    for (int j = 0; j < 8; j++)
        #pragma unroll
        for (int r = 0; r < 4; r++) pv[j][r] = 0.f;

    for (int it = tlo; it <= thi; it++) {
        int buf = (it - tlo) & 1;
        CP_WAIT0();
        __syncthreads();

        // prefetch next tile into other buffer
        if (it + 1 <= thi) {
            int col0n = (it + 1) * 64;
            uint32_t dst = sbase + AT_SM_KV + (buf ^ 1) * AT_SM_BUF;
            #pragma unroll
            for (int c = 0; c < 4; c++) {
                int ch = cb0 + c;
                uint32_t so = (uint32_t)(lrow * KPAD + ch * 8) * 2;
                CP_ASYNC16(dst + so,                  gKh + (size_t)(col0n + lrow) * DH + ch * 8);
                CP_ASYNC16(dst + AT_SM_TILE + so,     gKl + (size_t)(col0n + lrow) * DH + ch * 8);
                CP_ASYNC16(dst + 2 * AT_SM_TILE + so, gVh + (size_t)lrow * L_ + col0n + ch * 8);
                CP_ASYNC16(dst + 3 * AT_SM_TILE + so, gVl + (size_t)lrow * L_ + col0n + ch * 8);
            }
            if (tid < 64)
                ((int*)(sm + AT_SM_SK))[(buf ^ 1) * 64 + tid] =
                    seq_id[b * L_ + col0n + tid];
        }
        CP_COMMIT();

        const __nv_bfloat16* sKh = (const __nv_bfloat16*)(sm + AT_SM_KV + buf * AT_SM_BUF);
        const __nv_bfloat16* sKl = sKh + 4608;
        const __nv_bfloat16* sVh = sKh + 9216;
        const __nv_bfloat16* sVl = sKh + 13824;
        const int* skp = (const int*)(sm + AT_SM_SK) + buf * 64;

        // ---- S = Q K^T (split-3) ----
        float sf[8][4];
        #pragma unroll
        for (int j = 0; j < 8; j++)
            #pragma unroll
            for (int r = 0; r < 4; r++) sf[j][r] = 0.f;
        #pragma unroll
        for (int s = 0; s < 4; s++) {
            #pragma unroll
            for (int j = 0; j < 8; j++) {
                int off = (j * 8 + (lane >> 2)) * KPAD + s * 16 + (lane & 3) * 2;
                uint32_t bhf[2] = {*(const uint32_t*)(sKh + off),
                                   *(const uint32_t*)(sKh + off + 8)};
                uint32_t blf[2] = {*(const uint32_t*)(sKl + off),
                                   *(const uint32_t*)(sKl + off + 8)};
                MMA16816(sf[j], qfh[s], bhf);
                MMA16816(sf[j], qfh[s], blf);
                MMA16816(sf[j], qfl[s], bhf);
            }
        }

        // ---- mask + online softmax (c-frag layout) ----
        int colb = (lane & 3) * 2;
        float nm0 = m0, nm1 = m1;
        #pragma unroll
        for (int j = 0; j < 8; j++) {
            int k0 = skp[8 * j + colb], k1 = skp[8 * j + colb + 1];
            sf[j][0] = (k0 == sq0) ? sf[j][0] : -2e30f;
            sf[j][1] = (k1 == sq0) ? sf[j][1] : -2e30f;
            sf[j][2] = (k0 == sq1) ? sf[j][2] : -2e30f;
            sf[j][3] = (k1 == sq1) ? sf[j][3] : -2e30f;
            nm0 = fmaxf(nm0, fmaxf(sf[j][0], sf[j][1]));
            nm1 = fmaxf(nm1, fmaxf(sf[j][2], sf[j][3]));
        }
        nm0 = fmaxf(nm0, __shfl_xor_sync(0xffffffffu, nm0, 1));
        nm0 = fmaxf(nm0, __shfl_xor_sync(0xffffffffu, nm0, 2));
        nm1 = fmaxf(nm1, __shfl_xor_sync(0xffffffffu, nm1, 1));
        nm1 = fmaxf(nm1, __shfl_xor_sync(0xffffffffu, nm1, 2));
        float a0 = __expf(m0 - nm0), a1 = __expf(m1 - nm1);
        m0 = nm0; m1 = nm1;

        float s0 = 0.f, s1 = 0.f;
        uint32_t ph[4][4], pl[4][4];
        #pragma unroll
        for (int j = 0; j < 8; j++) {
            float p0 = __expf(sf[j][0] - m0), p1 = __expf(sf[j][1] - m0);
            float p2 = __expf(sf[j][2] - m1), p3 = __expf(sf[j][3] - m1);
            s0 += p0 + p1; s1 += p2 + p3;
            __nv_bfloat162 h01 = __float22bfloat162_rn(make_float2(p0, p1));
            float2 f01 = __bfloat1622float2(h01);
            __nv_bfloat162 l01 = __float22bfloat162_rn(make_float2(p0 - f01.x, p1 - f01.y));
            __nv_bfloat162 h23 = __float22bfloat162_rn(make_float2(p2, p3));
            float2 f23 = __bfloat1622float2(h23);
            __nv_bfloat162 l23 = __float22bfloat162_rn(make_float2(p2 - f23.x, p3 - f23.y));
            int s_ = j >> 1;
            int o  = (j & 1) * 2;
            ph[s_][o]     = *(uint32_t*)&h01;
            ph[s_][o + 1] = *(uint32_t*)&h23;
            pl[s_][o]     = *(uint32_t*)&l01;
            pl[s_][o + 1] = *(uint32_t*)&l23;
        }
        s0 += __shfl_xor_sync(0xffffffffu, s0, 1);
        s0 += __shfl_xor_sync(0xffffffffu, s0, 2);
        s1 += __shfl_xor_sync(0xffffffffu, s1, 1);
        s1 += __shfl_xor_sync(0xffffffffu, s1, 2);
        l0 = l0 * a0 + s0;
        l1 = l1 * a1 + s1;
        #pragma unroll
        for (int j = 0; j < 8; j++) {
            pv[j][0] *= a0; pv[j][1] *= a0; pv[j][2] *= a1; pv[j][3] *= a1;
        }

        // ---- PV (split-3), B = Vt[dh][c] ----
        #pragma unroll
        for (int s = 0; s < 4; s++) {
            #pragma unroll
            for (int j = 0; j < 8; j++) {
                int off = (j * 8 + (lane >> 2)) * KPAD + s * 16 + (lane & 3) * 2;
                uint32_t bhf[2] = {*(const uint32_t*)(sVh + off),
                                   *(const uint32_t*)(sVh + off + 8)};
                uint32_t blf[2] = {*(const uint32_t*)(sVl + off),
                                   *(const uint32_t*)(sVl + off + 8)};
                MMA16816(pv[j], ph[s], bhf);
                MMA16816(pv[j], ph[s], blf);
                MMA16816(pv[j], pl[s], bhf);
            }
        }
    }

    // ---- epilogue: ctx / l -> bf16 hi/lo [B,L,H,DH] ----
    float inv0 = 1.0f / l0, inv1 = 1.0f / l1;
    int r0g = row0 + w * 16 + (lane >> 2);
    #pragma unroll
    for (int j = 0; j < 8; j++) {
        int c = 8 * j + (lane & 3) * 2;
        size_t o0 = (((size_t)b * L_ + r0g) * H_ + h) * DH + c;
        size_t o1 = (((size_t)b * L_ + r0g + 8) * H_ + h) * DH + c;
        float x0 = pv[j][0] * inv0, x1 = pv[j][1] * inv0;
        float y0 = pv[j][2] * inv1, y1 = pv[j][3] * inv1;
        __nv_bfloat162 hx = __float22bfloat162_rn(make_float2(x0, x1));
        float2 fx = __bfloat1622float2(hx);
        __nv_bfloat162 lx = __float22bfloat162_rn(make_float2(x0 - fx.x, x1 - fx.y));
        __nv_bfloat162 hy = __float22bfloat162_rn(make_float2(y0, y1));
        float2 fy = __bfloat1622float2(hy);
        __nv_bfloat162 ly = __float22bfloat162_rn(make_float2(y0 - fy.x, y1 - fy.y));
        *(uint32_t*)&g_ch[o0] = *(uint32_t*)&hx;
        *(uint32_t*)&g_cl[o0] = *(uint32_t*)&lx;
        *(uint32_t*)&g_ch[o1] = *(uint32_t*)&hy;
        *(uint32_t*)&g_cl[o1] = *(uint32_t*)&ly;
    }
}

// ---------------- launch ----------------
extern "C" void kernel_launch(void* const* d_in, const int* in_sizes, int n_in,
                              void* d_out, int out_size) {
    const float* x      = (const float*)d_in[0];
    const int*   seq_id = (const int*)  d_in[1];
    const float* ln1_w  = (const float*)d_in[2];
    const float* ln1_b  = (const float*)d_in[3];
    const float* w_qkv  = (const float*)d_in[4];
    const float* q_ln_w = (const float*)d_in[5];
    const float* k_ln_w = (const float*)d_in[6];
    const float* out_w  = (const float*)d_in[7];
    float* out = (float*)d_out;

    void *phh, *phl, *pwqh, *pwql, *powh, *powl, *pch, *pcl, *pqkv;
    cudaGetSymbolAddress(&phh,  g_hh);
    cudaGetSymbolAddress(&phl,  g_hl);
    cudaGetSymbolAddress(&pwqh, g_wqh);
    cudaGetSymbolAddress(&pwql, g_wql);
    cudaGetSymbolAddress(&powh, g_owh);
    cudaGetSymbolAddress(&powl, g_owl);
    cudaGetSymbolAddress(&pch,  g_ch);
    cudaGetSymbolAddress(&pcl,  g_cl);
    cudaGetSymbolAddress(&pqkv, g_qkv);

    cudaFuncSetAttribute(attn_mma, cudaFuncAttributeMaxDynamicSharedMemorySize,
                         ATT2_SMEM);
    cudaFuncSetAttribute(gemm_mma, cudaFuncAttributeMaxDynamicSharedMemorySize,
                         GEMM_SMEM_BYTES);

    rope_table_kernel<<<(L_ * 32 + 255) / 256, 256>>>();
    split_kernel<<<(D3 * D_) / 1024, 256>>>(w_qkv, (__nv_bfloat16*)pwqh,
                                            (__nv_bfloat16*)pwql);
    split_kernel<<<(D_ * D_) / 1024, 256>>>(out_w, (__nv_bfloat16*)powh,
                                            (__nv_bfloat16*)powl);
    ln1_kernel<<<NT, 256>>>(x, ln1_w, ln1_b);
    gemm_mma<<<dim3(D3 / 128, NT / 128), 256, GEMM_SMEM_BYTES>>>(
        (const __nv_bfloat16*)phh, (const __nv_bfloat16*)phl,
        (const __nv_bfloat16*)pwqh, (const __nv_bfloat16*)pwql,
        (float*)pqkv, NT, D3, D_);
    qk_rope_kernel<<<NT, 256>>>(q_ln_w, k_ln_w);
    vt_kernel<<<dim3(L_ / 32, B_ * H_), 256>>>();
    attn_mma<<<dim3(L_ / 64, H_, B_), 128, ATT2_SMEM>>>(seq_id);
    gemm_mma<<<dim3(D_ / 128, NT / 128), 256, GEMM_SMEM_BYTES>>>(
        (const __nv_bfloat16*)pch, (const __nv_bfloat16*)pcl,
        (const __nv_bfloat16*)powh, (const __nv_bfloat16*)powl,
        out, NT, D_, D_);
}

// round 10
// speedup vs baseline: 2.9145x; 1.7735x over previous
#include <cuda_runtime.h>
#include <cuda_bf16.h>
#include <cuda_fp16.h>
#include <cstdint>
#include <math.h>

// Problem constants
#define B_  2
#define L_  2048
#define NT  4096            // B*L tokens
#define D_  1024
#define H_  16
#define DH  64
#define D3  3072
#define EPS 1e-5f

// ---------------- scratch (device globals; no allocation) ----------------
__device__ __half g_hf[NT * D_];          // LN1 out (fp16)
__device__ __half g_wqf[D3 * D_];         // w_qkv (fp16)
__device__ __half g_owf[D_ * D_];         // out_w (fp16)
__device__ __half g_cf[NT * D_];          // ctx (fp16) [B,L,H,DH] == [NT,D]
__device__ __nv_bfloat16 g_qh[NT * D_];   // q (scaled) hi  [BH,L,DH]
__device__ __nv_bfloat16 g_ql[NT * D_];
__device__ __nv_bfloat16 g_kh[NT * D_];   // k hi [BH,L,DH]
__device__ __nv_bfloat16 g_kl[NT * D_];
__device__ __nv_bfloat16 g_vth[NT * D_];  // v^T hi [BH,DH,L]
__device__ __nv_bfloat16 g_vtl[NT * D_];
__device__ float g_qkv[NT * D3];          // QKV gemm output [NT, 3D]
__device__ float g_cos[L_ * 32];
__device__ float g_sin[L_ * 32];

// ---------------- helpers ----------------
__device__ __forceinline__ uint32_t smem_u32(const void* p) {
    uint32_t a;
    asm("{ .reg .u64 t; cvta.to.shared.u64 t, %1; cvt.u32.u64 %0, t; }"
        : "=r"(a) : "l"(p));
    return a;
}
#define CP_ASYNC16(dst, src) \
    asm volatile("cp.async.cg.shared.global [%0], [%1], 16;" :: "r"(dst), "l"(src))
#define CP_COMMIT() asm volatile("cp.async.commit_group;" ::: "memory")
#define CP_WAIT0()  asm volatile("cp.async.wait_group 0;" ::: "memory")
#define CP_WAIT1()  asm volatile("cp.async.wait_group 1;" ::: "memory")

// bf16 mma (attention)
#define MMA16816(d, a, b) \
    asm volatile( \
        "mma.sync.aligned.m16n8k16.row.col.f32.bf16.bf16.f32 " \
        "{%0,%1,%2,%3}, {%4,%5,%6,%7}, {%8,%9}, {%0,%1,%2,%3};" \
        : "+f"((d)[0]), "+f"((d)[1]), "+f"((d)[2]), "+f"((d)[3]) \
        : "r"((a)[0]), "r"((a)[1]), "r"((a)[2]), "r"((a)[3]), \
          "r"((b)[0]), "r"((b)[1]))

// fp16 mma (dense GEMMs)
#define MMAF16(d, a, b) \
    asm volatile( \
        "mma.sync.aligned.m16n8k16.row.col.f32.f16.f16.f32 " \
        "{%0,%1,%2,%3}, {%4,%5,%6,%7}, {%8,%9}, {%0,%1,%2,%3};" \
        : "+f"((d)[0]), "+f"((d)[1]), "+f"((d)[2]), "+f"((d)[3]) \
        : "r"((a)[0]), "r"((a)[1]), "r"((a)[2]), "r"((a)[3]), \
          "r"((b)[0]), "r"((b)[1]))

// ---------------- RoPE table ----------------
__global__ void rope_table_kernel() {
    int idx = blockIdx.x * blockDim.x + threadIdx.x;
    if (idx >= L_ * 32) return;
    int l = idx >> 5;
    int j = idx & 31;
    float inv = powf(10000.0f, -(float)j / 32.0f);
    float ang = (float)l * inv;
    float s, c;
    sincosf(ang, &s, &c);
    g_cos[idx] = c;
    g_sin[idx] = s;
}

// ---------------- fp32 -> fp16 convert (weights) ----------------
__global__ void conv16_kernel(const float* __restrict__ x,
                              __half* __restrict__ y) {
    int i = (blockIdx.x * 256 + threadIdx.x) * 4;
    float4 v = *(const float4*)&x[i];
    __half2 a = __floats2half2_rn(v.x, v.y);
    __half2 b = __floats2half2_rn(v.z, v.w);
    uint2 u;
    u.x = *(uint32_t*)&a;
    u.y = *(uint32_t*)&b;
    *(uint2*)&y[i] = u;
}

// ---------------- LN1 -> fp16 ----------------
__global__ void ln1_kernel(const float* __restrict__ x,
                           const float* __restrict__ w,
                           const float* __restrict__ b) {
    int n = blockIdx.x;
    const float* xr = x + (size_t)n * D_;
    int t = threadIdx.x;
    float4 v = *(const float4*)&xr[t * 4];
    float s  = v.x + v.y + v.z + v.w;
    float s2 = v.x*v.x + v.y*v.y + v.z*v.z + v.w*v.w;
    #pragma unroll
    for (int o = 16; o >= 1; o >>= 1) {
        s  += __shfl_xor_sync(0xffffffffu, s,  o);
        s2 += __shfl_xor_sync(0xffffffffu, s2, o);
    }
    __shared__ float red[2][8];
    int lane = t & 31, wp = t >> 5;
    if (lane == 0) { red[0][wp] = s; red[1][wp] = s2; }
    __syncthreads();
    __shared__ float stat[2];
    if (t == 0) {
        float a = 0.f, c = 0.f;
        #pragma unroll
        for (int i = 0; i < 8; i++) { a += red[0][i]; c += red[1][i]; }
        float mu  = a * (1.0f / D_);
        float var = c * (1.0f / D_) - mu * mu;
        stat[0] = mu;
        stat[1] = rsqrtf(var + EPS);
    }
    __syncthreads();
    float mu = stat[0], rs = stat[1];
    float4 wv = *(const float4*)&w[t * 4];
    float4 bv = *(const float4*)&b[t * 4];
    float o0 = (v.x - mu) * rs * wv.x + bv.x;
    float o1 = (v.y - mu) * rs * wv.y + bv.y;
    float o2 = (v.z - mu) * rs * wv.z + bv.z;
    float o3 = (v.w - mu) * rs * wv.w + bv.w;
    __half2 a = __floats2half2_rn(o0, o1);
    __half2 bb = __floats2half2_rn(o2, o3);
    uint2 u;
    u.x = *(uint32_t*)&a;
    u.y = *(uint32_t*)&bb;
    *(uint2*)&g_hf[(size_t)n * D_ + t * 4] = u;
}

// ============ warp-MMA fp16 GEMM: C[M,N] = A[M,K]*B[N,K]^T (fp32 accum) ============
// CTA 128x128, 8 warps of 64x32. 3 stages x K32 chunks, one sync per chunk.
#define GSUB   (128 * 16)                 // fp16 elems per K16 sub-buffer
#define GSTG   (2 * GSUB)                 // elems per stage (2 subs, K32)
#define GMAT   (3 * GSTG)                 // elems per matrix (3 stages)
#define GEMM_SMEM_BYTES (2 * GMAT * 2)    // 49152 B

__global__ __launch_bounds__(256) void gemm_f16(
    const __half* __restrict__ Af, const __half* __restrict__ Bf,
    float* __restrict__ C, int M, int N, int K)
{
    extern __shared__ __half smg[];
    __half* sA = smg;                   // [3][2 subs][128*16]
    __half* sB = smg + GMAT;

    int tid = threadIdx.x;
    int warp = tid >> 5, lane = tid & 31;
    int m0 = blockIdx.y * 128, n0 = blockIdx.x * 128;
    int wm = (warp & 1) * 64, wn = (warp >> 1) * 32;

    int lrow = tid >> 1;
    int lch  = (tid & 1) * 8;
    uint32_t uA = smem_u32(sA), uB = smem_u32(sB);
    uint32_t dsto = (uint32_t)(lrow * 16 + lch) * 2;    // within a sub buffer

    const __half* gA = Af + (size_t)(m0 + lrow) * K + lch;
    const __half* gB = Bf + (size_t)(n0 + lrow) * K + lch;

    float d[4][4][4];
    #pragma unroll
    for (int mi = 0; mi < 4; mi++)
        #pragma unroll
        for (int ni = 0; ni < 4; ni++)
            #pragma unroll
            for (int r = 0; r < 4; r++) d[mi][ni][r] = 0.f;

    const int nchunk = K >> 5;          // K32 chunks

    // prologue: chunks 0,1 -> stages 0,1
    #pragma unroll
    for (int c = 0; c < 2; c++) {
        #pragma unroll
        for (int sub = 0; sub < 2; sub++) {
            uint32_t so = (uint32_t)(c * GSTG + sub * GSUB) * 2 + dsto;
            CP_ASYNC16(uA + so, gA + c * 32 + sub * 16);
            CP_ASYNC16(uB + so, gB + c * 32 + sub * 16);
        }
        CP_COMMIT();
    }

    int ar = wm + (lane >> 2);
    int ac = (lane & 3) * 2;
    int br = wn + (lane >> 2);
    int bc = (lane & 3) * 2;

    for (int c = 0; c < nchunk; c++) {
        int st = c % 3;
        if (c == nchunk - 1) { CP_WAIT0(); } else { CP_WAIT1(); }
        __syncthreads();

        // prefetch chunk c+2 into stage (c+2)%3 (disjoint from live stages)
        if (c + 2 < nchunk) {
            int sn = (c + 2) % 3;
            #pragma unroll
            for (int sub = 0; sub < 2; sub++) {
                uint32_t so = (uint32_t)(sn * GSTG + sub * GSUB) * 2 + dsto;
                CP_ASYNC16(uA + so, gA + (c + 2) * 32 + sub * 16);
                CP_ASYNC16(uB + so, gB + (c + 2) * 32 + sub * 16);
            }
        }
        CP_COMMIT();

        #pragma unroll
        for (int sub = 0; sub < 2; sub++) {
            const __half* pA = sA + st * GSTG + sub * GSUB;
            const __half* pB = sB + st * GSTG + sub * GSUB;

            uint32_t ah[4][4], bh[4][2];
            #pragma unroll
            for (int mi = 0; mi < 4; mi++) {
                int r0 = (ar + mi * 16) * 16 + ac;
                int r1 = r0 + 8 * 16;
                ah[mi][0] = *(const uint32_t*)(pA + r0);
                ah[mi][1] = *(const uint32_t*)(pA + r1);
                ah[mi][2] = *(const uint32_t*)(pA + r0 + 8);
                ah[mi][3] = *(const uint32_t*)(pA + r1 + 8);
            }
            #pragma unroll
            for (int ni = 0; ni < 4; ni++) {
                int c0 = (br + ni * 8) * 16 + bc;
                bh[ni][0] = *(const uint32_t*)(pB + c0);
                bh[ni][1] = *(const uint32_t*)(pB + c0 + 8);
            }

            #pragma unroll
            for (int mi = 0; mi < 4; mi++)
                #pragma unroll
                for (int ni = 0; ni < 4; ni++)
                    MMAF16(d[mi][ni], ah[mi], bh[ni]);
        }
    }

    #pragma unroll
    for (int mi = 0; mi < 4; mi++) {
        int r = m0 + wm + mi * 16 + (lane >> 2);
        #pragma unroll
        for (int ni = 0; ni < 4; ni++) {
            int c = n0 + wn + ni * 8 + (lane & 3) * 2;
            *(float2*)&C[(size_t)r * N + c] = make_float2(d[mi][ni][0], d[mi][ni][1]);
            *(float2*)&C[(size_t)(r + 8) * N + c] = make_float2(d[mi][ni][2], d[mi][ni][3]);
        }
    }
}

// ---------------- fused QK-LN + RoPE -> bf16 hi/lo [BH,L,DH] ----------------
__global__ void qk_rope_kernel(const float* __restrict__ qw,
                               const float* __restrict__ kw) {
    int n = blockIdx.x;
    int b = n >> 11;
    int l = n & 2047;
    const float* q = g_qkv + (size_t)n * D3;
    const float* k = q + D_;
    int t = threadIdx.x;

    float4 qv = *(const float4*)&q[t * 4];
    float4 kv = *(const float4*)&k[t * 4];
    float qs  = qv.x + qv.y + qv.z + qv.w;
    float qs2 = qv.x*qv.x + qv.y*qv.y + qv.z*qv.z + qv.w*qv.w;
    float ks  = kv.x + kv.y + kv.z + kv.w;
    float ks2 = kv.x*kv.x + kv.y*kv.y + kv.z*kv.z + kv.w*kv.w;
    #pragma unroll
    for (int o = 16; o >= 1; o >>= 1) {
        qs  += __shfl_xor_sync(0xffffffffu, qs,  o);
        qs2 += __shfl_xor_sync(0xffffffffu, qs2, o);
        ks  += __shfl_xor_sync(0xffffffffu, ks,  o);
        ks2 += __shfl_xor_sync(0xffffffffu, ks2, o);
    }
    __shared__ float red[4][8];
    __shared__ float stat[4];
    __shared__ float qn[D_], kn[D_];
    int lane = t & 31, wp = t >> 5;
    if (lane == 0) { red[0][wp]=qs; red[1][wp]=qs2; red[2][wp]=ks; red[3][wp]=ks2; }
    __syncthreads();
    if (t == 0) {
        float a=0,c=0,e=0,f=0;
        #pragma unroll
        for (int i=0;i<8;i++){a+=red[0][i];c+=red[1][i];e+=red[2][i];f+=red[3][i];}
        float qmu=a*(1.f/D_), qvr=c*(1.f/D_)-qmu*qmu;
        float kmu=e*(1.f/D_), kvr=f*(1.f/D_)-kmu*kmu;
        stat[0]=qmu; stat[1]=rsqrtf(qvr+EPS);
        stat[2]=kmu; stat[3]=rsqrtf(kvr+EPS);
    }
    __syncthreads();
    float qmu=stat[0], qrs=stat[1], kmu=stat[2], krs=stat[3];
    float4 qwv = *(const float4*)&qw[t*4];
    float4 kwv = *(const float4*)&kw[t*4];
    qn[t*4+0]=(qv.x-qmu)*qrs*qwv.x; qn[t*4+1]=(qv.y-qmu)*qrs*qwv.y;
    qn[t*4+2]=(qv.z-qmu)*qrs*qwv.z; qn[t*4+3]=(qv.w-qmu)*qrs*qwv.w;
    kn[t*4+0]=(kv.x-kmu)*krs*kwv.x; kn[t*4+1]=(kv.y-kmu)*krs*kwv.y;
    kn[t*4+2]=(kv.z-kmu)*krs*kwv.z; kn[t*4+3]=(kv.w-kmu)*krs*kwv.w;
    __syncthreads();

    int d0 = t * 4;
    int hh = d0 >> 6;
    int j0 = d0 & 63;
    float qo[4], ko[4];
    #pragma unroll
    for (int ii = 0; ii < 4; ii++) {
        int d = d0 + ii;
        int j = j0 + ii;
        int f = j & 31;
        float c = g_cos[l * 32 + f];
        float s = g_sin[l * 32 + f];
        if (j < 32) {
            qo[ii] = qn[d] * c - qn[d + 32] * s;
            ko[ii] = kn[d] * c - kn[d + 32] * s;
        } else {
            qo[ii] = qn[d] * c + qn[d - 32] * s;
            ko[ii] = kn[d] * c + kn[d - 32] * s;
        }
        qo[ii] *= 0.125f;   // fold softmax scale into q
    }
    size_t oidx = (((size_t)(b * H_ + hh)) * L_ + l) * DH + j0;
    union { __nv_bfloat16 h[4]; uint2 u; } uqh, uql, ukh, ukl;
    #pragma unroll
    for (int ii = 0; ii < 4; ii++) {
        __nv_bfloat16 hb = __float2bfloat16(qo[ii]);
        uqh.h[ii] = hb;
        uql.h[ii] = __float2bfloat16(qo[ii] - __bfloat162float(hb));
        __nv_bfloat16 kb = __float2bfloat16(ko[ii]);
        ukh.h[ii] = kb;
        ukl.h[ii] = __float2bfloat16(ko[ii] - __bfloat162float(kb));
    }
    *(uint2*)&g_qh[oidx] = uqh.u;
    *(uint2*)&g_ql[oidx] = uql.u;
    *(uint2*)&g_kh[oidx] = ukh.u;
    *(uint2*)&g_kl[oidx] = ukl.u;
}

// ---------------- V transpose: g_qkv v-part -> [BH,DH,L] bf16 hi/lo ----------------
__global__ void vt_kernel() {
    __shared__ float tile[64][33];
    int bh = blockIdx.y;
    int b = bh >> 4, h = bh & 15;
    int l0 = blockIdx.x * 32;
    int tx = threadIdx.x & 31, ty = threadIdx.x >> 5;   // 256 threads

    #pragma unroll
    for (int i = 0; i < 4; i++) {
        int l = l0 + ty + i * 8;
        const float* row = g_qkv + (size_t)(b * L_ + l) * D3 + 2 * D_ + h * DH;
        tile[tx][ty + i * 8]      = row[tx];
        tile[tx + 32][ty + i * 8] = row[tx + 32];
    }
    __syncthreads();
    #pragma unroll
    for (int i = 0; i < 8; i++) {
        int d = ty + i * 8;
        float v = tile[d][tx];
        __nv_bfloat16 hb = __float2bfloat16(v);
        __nv_bfloat16 lb = __float2bfloat16(v - __bfloat162float(hb));
        size_t o = (size_t)(bh * DH + d) * L_ + l0 + tx;
        g_vth[o] = hb;
        g_vtl[o] = lb;
    }
}

// ---------------- flash attention on mma.sync (bf16 split-3) ----------------
// Block-diagonal mask: seq_id sorted -> valid k-tiles form a contiguous range.
#define KPAD 72
#define AT_SM_QH 0
#define AT_SM_QL 9216
#define AT_SM_KV 18432
#define AT_SM_TILE 9216
#define AT_SM_BUF 36864
#define AT_SM_SK (18432 + 2 * 36864)
#define ATT2_SMEM (AT_SM_SK + 512)

__global__ __launch_bounds__(128) void attn_mma(const int* __restrict__ seq_id) {
    extern __shared__ char sm[];
    const uint32_t sbase = smem_u32(sm);
    int tid = threadIdx.x, lane = tid & 31, w = tid >> 5;
    int qt = blockIdx.x, h = blockIdx.y, b = blockIdx.z;
    int bh = b * H_ + h;
    int row0 = qt * 64;

    const __nv_bfloat16* gQh = g_qh + ((size_t)bh * L_ + row0) * DH;
    const __nv_bfloat16* gQl = g_ql + ((size_t)bh * L_ + row0) * DH;
    const __nv_bfloat16* gKh = g_kh + (size_t)bh * L_ * DH;
    const __nv_bfloat16* gKl = g_kl + (size_t)bh * L_ * DH;
    const __nv_bfloat16* gVh = g_vth + (size_t)bh * DH * L_;
    const __nv_bfloat16* gVl = g_vtl + (size_t)bh * DH * L_;

    // ---- valid k-tile range (contiguous because seq_id is sorted) ----
    int q_lo = seq_id[b * L_ + row0];
    int q_hi = seq_id[b * L_ + row0 + 63];
    unsigned vmask;
    {
        int klo = seq_id[b * L_ + lane * 64];
        int khi = seq_id[b * L_ + lane * 64 + 63];
        bool ok = (khi >= q_lo) && (klo <= q_hi);
        vmask = __ballot_sync(0xffffffffu, ok);
    }
    int tlo = __ffs(vmask) - 1;
    int thi = 31 - __clz(vmask);

    int lrow = tid >> 1;          // 0..63
    int cb0  = (tid & 1) * 4;     // chunk base (16B chunks)

    // ---- prologue: Q tiles ----
    #pragma unroll
    for (int c = 0; c < 4; c++) {
        int ch = cb0 + c;
        uint32_t so = (uint32_t)(lrow * KPAD + ch * 8) * 2;
        CP_ASYNC16(sbase + AT_SM_QH + so, gQh + lrow * DH + ch * 8);
        CP_ASYNC16(sbase + AT_SM_QL + so, gQl + lrow * DH + ch * 8);
    }
    CP_COMMIT();
    // ---- K/V tile tlo ----
    {
        int col0 = tlo * 64;
        uint32_t dst = sbase + AT_SM_KV;
        #pragma unroll
        for (int c = 0; c < 4; c++) {
            int ch = cb0 + c;
            uint32_t so = (uint32_t)(lrow * KPAD + ch * 8) * 2;
            CP_ASYNC16(dst + so,                  gKh + (size_t)(col0 + lrow) * DH + ch * 8);
            CP_ASYNC16(dst + AT_SM_TILE + so,     gKl + (size_t)(col0 + lrow) * DH + ch * 8);
            CP_ASYNC16(dst + 2 * AT_SM_TILE + so, gVh + (size_t)lrow * L_ + col0 + ch * 8);
            CP_ASYNC16(dst + 3 * AT_SM_TILE + so, gVl + (size_t)lrow * L_ + col0 + ch * 8);
        }
    }
    CP_COMMIT();
    if (tid < 64) ((int*)(sm + AT_SM_SK))[tid] = seq_id[b * L_ + tlo * 64 + tid];
    int sq0 = seq_id[b * L_ + row0 + w * 16 + (lane >> 2)];
    int sq1 = seq_id[b * L_ + row0 + w * 16 + (lane >> 2) + 8];

    CP_WAIT1();
    __syncthreads();

    // ---- extract Q fragments (held for whole kernel) ----
    uint32_t qfh[4][4], qfl[4][4];
    {
        const __nv_bfloat16* sQh = (const __nv_bfloat16*)(sm + AT_SM_QH);
        const __nv_bfloat16* sQl = (const __nv_bfloat16*)(sm + AT_SM_QL);
        #pragma unroll
        for (int s = 0; s < 4; s++) {
            int base = (w * 16 + (lane >> 2)) * KPAD + s * 16 + (lane & 3) * 2;
            qfh[s][0] = *(const uint32_t*)(sQh + base);
            qfh[s][1] = *(const uint32_t*)(sQh + base + 8 * KPAD);
            qfh[s][2] = *(const uint32_t*)(sQh + base + 8);
            qfh[s][3] = *(const uint32_t*)(sQh + base + 8 * KPAD + 8);
            qfl[s][0] = *(const uint32_t*)(sQl + base);
            qfl[s][1] = *(const uint32_t*)(sQl + base + 8 * KPAD);
            qfl[s][2] = *(const uint32_t*)(sQl + base + 8);
            qfl[s][3] = *(const uint32_t*)(sQl + base + 8 * KPAD + 8);
        }
    }

    float m0 = -1e30f, m1 = -1e30f, l0 = 0.f, l1 = 0.f;
    float pv[8][4];
    #pragma unroll
    for (int j = 0; j < 8; j++)
        #pragma unroll
        for (int r = 0; r < 4; r++) pv[j][r] = 0.f;

    for (int it = tlo; it <= thi; it++) {
        int buf = (it - tlo) & 1;
        CP_WAIT0();
        __syncthreads();

        // prefetch next tile into other buffer
        if (it + 1 <= thi) {
            int col0n = (it + 1) * 64;
            uint32_t dst = sbase + AT_SM_KV + (buf ^ 1) * AT_SM_BUF;
            #pragma unroll
            for (int c = 0; c < 4; c++) {
                int ch = cb0 + c;
                uint32_t so = (uint32_t)(lrow * KPAD + ch * 8) * 2;
                CP_ASYNC16(dst + so,                  gKh + (size_t)(col0n + lrow) * DH + ch * 8);
                CP_ASYNC16(dst + AT_SM_TILE + so,     gKl + (size_t)(col0n + lrow) * DH + ch * 8);
                CP_ASYNC16(dst + 2 * AT_SM_TILE + so, gVh + (size_t)lrow * L_ + col0n + ch * 8);
                CP_ASYNC16(dst + 3 * AT_SM_TILE + so, gVl + (size_t)lrow * L_ + col0n + ch * 8);
            }
            if (tid < 64)
                ((int*)(sm + AT_SM_SK))[(buf ^ 1) * 64 + tid] =
                    seq_id[b * L_ + col0n + tid];
        }
        CP_COMMIT();

        const __nv_bfloat16* sKh = (const __nv_bfloat16*)(sm + AT_SM_KV + buf * AT_SM_BUF);
        const __nv_bfloat16* sKl = sKh + 4608;
        const __nv_bfloat16* sVh = sKh + 9216;
        const __nv_bfloat16* sVl = sKh + 13824;
        const int* skp = (const int*)(sm + AT_SM_SK) + buf * 64;

        // ---- S = Q K^T (split-3) ----
        float sf[8][4];
        #pragma unroll
        for (int j = 0; j < 8; j++)
            #pragma unroll
            for (int r = 0; r < 4; r++) sf[j][r] = 0.f;
        #pragma unroll
        for (int s = 0; s < 4; s++) {
            #pragma unroll
            for (int j = 0; j < 8; j++) {
                int off = (j * 8 + (lane >> 2)) * KPAD + s * 16 + (lane & 3) * 2;
                uint32_t bhf[2] = {*(const uint32_t*)(sKh + off),
                                   *(const uint32_t*)(sKh + off + 8)};
                uint32_t blf[2] = {*(const uint32_t*)(sKl + off),
                                   *(const uint32_t*)(sKl + off + 8)};
                MMA16816(sf[j], qfh[s], bhf);
                MMA16816(sf[j], qfh[s], blf);
                MMA16816(sf[j], qfl[s], bhf);
            }
        }

        // ---- mask + online softmax (c-frag layout) ----
        int colb = (lane & 3) * 2;
        float nm0 = m0, nm1 = m1;
        #pragma unroll
        for (int j = 0; j < 8; j++) {
            int k0 = skp[8 * j + colb], k1 = skp[8 * j + colb + 1];
            sf[j][0] = (k0 == sq0) ? sf[j][0] : -2e30f;
            sf[j][1] = (k1 == sq0) ? sf[j][1] : -2e30f;
            sf[j][2] = (k0 == sq1) ? sf[j][2] : -2e30f;
            sf[j][3] = (k1 == sq1) ? sf[j][3] : -2e30f;
            nm0 = fmaxf(nm0, fmaxf(sf[j][0], sf[j][1]));
            nm1 = fmaxf(nm1, fmaxf(sf[j][2], sf[j][3]));
        }
        nm0 = fmaxf(nm0, __shfl_xor_sync(0xffffffffu, nm0, 1));
        nm0 = fmaxf(nm0, __shfl_xor_sync(0xffffffffu, nm0, 2));
        nm1 = fmaxf(nm1, __shfl_xor_sync(0xffffffffu, nm1, 1));
        nm1 = fmaxf(nm1, __shfl_xor_sync(0xffffffffu, nm1, 2));
        float a0 = __expf(m0 - nm0), a1 = __expf(m1 - nm1);
        m0 = nm0; m1 = nm1;

        float s0 = 0.f, s1 = 0.f;
        uint32_t ph[4][4], pl[4][4];
        #pragma unroll
        for (int j = 0; j < 8; j++) {
            float p0 = __expf(sf[j][0] - m0), p1 = __expf(sf[j][1] - m0);
            float p2 = __expf(sf[j][2] - m1), p3 = __expf(sf[j][3] - m1);
            s0 += p0 + p1; s1 += p2 + p3;
            __nv_bfloat162 h01 = __float22bfloat162_rn(make_float2(p0, p1));
            float2 f01 = __bfloat1622float2(h01);
            __nv_bfloat162 l01 = __float22bfloat162_rn(make_float2(p0 - f01.x, p1 - f01.y));
            __nv_bfloat162 h23 = __float22bfloat162_rn(make_float2(p2, p3));
            float2 f23 = __bfloat1622float2(h23);
            __nv_bfloat162 l23 = __float22bfloat162_rn(make_float2(p2 - f23.x, p3 - f23.y));
            int s_ = j >> 1;
            int o  = (j & 1) * 2;
            ph[s_][o]     = *(uint32_t*)&h01;
            ph[s_][o + 1] = *(uint32_t*)&h23;
            pl[s_][o]     = *(uint32_t*)&l01;
            pl[s_][o + 1] = *(uint32_t*)&l23;
        }
        s0 += __shfl_xor_sync(0xffffffffu, s0, 1);
        s0 += __shfl_xor_sync(0xffffffffu, s0, 2);
        s1 += __shfl_xor_sync(0xffffffffu, s1, 1);
        s1 += __shfl_xor_sync(0xffffffffu, s1, 2);
        l0 = l0 * a0 + s0;
        l1 = l1 * a1 + s1;
        #pragma unroll
        for (int j = 0; j < 8; j++) {
            pv[j][0] *= a0; pv[j][1] *= a0; pv[j][2] *= a1; pv[j][3] *= a1;
        }

        // ---- PV (split-3), B = Vt[dh][c] ----
        #pragma unroll
        for (int s = 0; s < 4; s++) {
            #pragma unroll
            for (int j = 0; j < 8; j++) {
                int off = (j * 8 + (lane >> 2)) * KPAD + s * 16 + (lane & 3) * 2;
                uint32_t bhf[2] = {*(const uint32_t*)(sVh + off),
                                   *(const uint32_t*)(sVh + off + 8)};
                uint32_t blf[2] = {*(const uint32_t*)(sVl + off),
                                   *(const uint32_t*)(sVl + off + 8)};
                MMA16816(pv[j], ph[s], bhf);
                MMA16816(pv[j], ph[s], blf);
                MMA16816(pv[j], pl[s], bhf);
            }
        }
    }

    // ---- epilogue: ctx / l -> fp16 [B,L,H,DH] ----
    float inv0 = 1.0f / l0, inv1 = 1.0f / l1;
    int r0g = row0 + w * 16 + (lane >> 2);
    #pragma unroll
    for (int j = 0; j < 8; j++) {
        int c = 8 * j + (lane & 3) * 2;
        size_t o0 = (((size_t)b * L_ + r0g) * H_ + h) * DH + c;
        size_t o1 = (((size_t)b * L_ + r0g + 8) * H_ + h) * DH + c;
        __half2 hx = __floats2half2_rn(pv[j][0] * inv0, pv[j][1] * inv0);
        __half2 hy = __floats2half2_rn(pv[j][2] * inv1, pv[j][3] * inv1);
        *(uint32_t*)&g_cf[o0] = *(uint32_t*)&hx;
        *(uint32_t*)&g_cf[o1] = *(uint32_t*)&hy;
    }
}

// ---------------- launch ----------------
extern "C" void kernel_launch(void* const* d_in, const int* in_sizes, int n_in,
                              void* d_out, int out_size) {
    const float* x      = (const float*)d_in[0];
    const int*   seq_id = (const int*)  d_in[1];
    const float* ln1_w  = (const float*)d_in[2];
    const float* ln1_b  = (const float*)d_in[3];
    const float* w_qkv  = (const float*)d_in[4];
    const float* q_ln_w = (const float*)d_in[5];
    const float* k_ln_w = (const float*)d_in[6];
    const float* out_w  = (const float*)d_in[7];
    float* out = (float*)d_out;

    void *phf, *pwqf, *powf, *pcf, *pqkv;
    cudaGetSymbolAddress(&phf,  g_hf);
    cudaGetSymbolAddress(&pwqf, g_wqf);
    cudaGetSymbolAddress(&powf, g_owf);
    cudaGetSymbolAddress(&pcf,  g_cf);
    cudaGetSymbolAddress(&pqkv, g_qkv);

    cudaFuncSetAttribute(attn_mma, cudaFuncAttributeMaxDynamicSharedMemorySize,
                         ATT2_SMEM);
    cudaFuncSetAttribute(gemm_f16, cudaFuncAttributeMaxDynamicSharedMemorySize,
                         GEMM_SMEM_BYTES);

    rope_table_kernel<<<(L_ * 32 + 255) / 256, 256>>>();
    conv16_kernel<<<(D3 * D_) / 1024, 256>>>(w_qkv, (__half*)pwqf);
    conv16_kernel<<<(D_ * D_) / 1024, 256>>>(out_w, (__half*)powf);
    ln1_kernel<<<NT, 256>>>(x, ln1_w, ln1_b);
    gemm_f16<<<dim3(D3 / 128, NT / 128), 256, GEMM_SMEM_BYTES>>>(
        (const __half*)phf, (const __half*)pwqf, (float*)pqkv, NT, D3, D_);
    qk_rope_kernel<<<NT, 256>>>(q_ln_w, k_ln_w);
    vt_kernel<<<dim3(L_ / 32, B_ * H_), 256>>>();
    attn_mma<<<dim3(L_ / 64, H_, B_), 128, ATT2_SMEM>>>(seq_id);
    gemm_f16<<<dim3(D_ / 128, NT / 128), 256, GEMM_SMEM_BYTES>>>(
        (const __half*)pcf, (const __half*)powf, out, NT, D_, D_);
}

// round 11
// speedup vs baseline: 3.1042x; 1.0651x over previous
#include <cuda_runtime.h>
#include <cuda_bf16.h>
#include <cuda_fp16.h>
#include <cstdint>
#include <math.h>

// Problem constants
#define B_  2
#define L_  2048
#define NT  4096            // B*L tokens
#define D_  1024
#define H_  16
#define DH  64
#define D3  3072
#define EPS 1e-5f

// ---------------- scratch (device globals; no allocation) ----------------
__device__ __half g_hf[NT * D_];          // LN1 out (fp16)
__device__ __half g_wqf[D3 * D_];         // w_qkv (fp16)
__device__ __half g_owf[D_ * D_];         // out_w (fp16)
__device__ __half g_cf[NT * D_];          // ctx (fp16) [B,L,H,DH] == [NT,D]
__device__ __nv_bfloat16 g_qh[NT * D_];   // q (scaled) hi  [BH,L,DH]
__device__ __nv_bfloat16 g_ql[NT * D_];
__device__ __nv_bfloat16 g_kh[NT * D_];   // k hi [BH,L,DH]
__device__ __nv_bfloat16 g_kl[NT * D_];
__device__ __nv_bfloat16 g_vth[NT * D_];  // v^T hi [BH,DH,L]
__device__ __nv_bfloat16 g_vtl[NT * D_];
__device__ float g_qkv[NT * D3];          // QKV gemm output [NT, 3D]
__device__ float g_cos[L_ * 32];
__device__ float g_sin[L_ * 32];

// ---------------- helpers ----------------
__device__ __forceinline__ uint32_t smem_u32(const void* p) {
    uint32_t a;
    asm("{ .reg .u64 t; cvta.to.shared.u64 t, %1; cvt.u32.u64 %0, t; }"
        : "=r"(a) : "l"(p));
    return a;
}
#define CP_ASYNC16(dst, src) \
    asm volatile("cp.async.cg.shared.global [%0], [%1], 16;" :: "r"(dst), "l"(src))
#define CP_COMMIT() asm volatile("cp.async.commit_group;" ::: "memory")
#define CP_WAIT0()  asm volatile("cp.async.wait_group 0;" ::: "memory")
#define CP_WAIT1()  asm volatile("cp.async.wait_group 1;" ::: "memory")

// bf16 mma (attention)
#define MMA16816(d, a, b) \
    asm volatile( \
        "mma.sync.aligned.m16n8k16.row.col.f32.bf16.bf16.f32 " \
        "{%0,%1,%2,%3}, {%4,%5,%6,%7}, {%8,%9}, {%0,%1,%2,%3};" \
        : "+f"((d)[0]), "+f"((d)[1]), "+f"((d)[2]), "+f"((d)[3]) \
        : "r"((a)[0]), "r"((a)[1]), "r"((a)[2]), "r"((a)[3]), \
          "r"((b)[0]), "r"((b)[1]))

// fp16 mma (dense GEMMs)
#define MMAF16(d, a, b) \
    asm volatile( \
        "mma.sync.aligned.m16n8k16.row.col.f32.f16.f16.f32 " \
        "{%0,%1,%2,%3}, {%4,%5,%6,%7}, {%8,%9}, {%0,%1,%2,%3};" \
        : "+f"((d)[0]), "+f"((d)[1]), "+f"((d)[2]), "+f"((d)[3]) \
        : "r"((a)[0]), "r"((a)[1]), "r"((a)[2]), "r"((a)[3]), \
          "r"((b)[0]), "r"((b)[1]))

// ---------------- fused prep: rope table + weight conv + LN1 ----------------
// grid: [0,256) rope | [256,3328) conv w_qkv | [3328,4352) conv out_w |
//       [4352,8448) ln1
__global__ void prep_kernel(const float* __restrict__ x,
                            const float* __restrict__ ln1w,
                            const float* __restrict__ ln1b,
                            const float* __restrict__ wq,
                            const float* __restrict__ ow) {
    int bid = blockIdx.x;
    int t = threadIdx.x;
    if (bid < 256) {
        int idx = bid * 256 + t;
        int l = idx >> 5;
        int j = idx & 31;
        float inv = powf(10000.0f, -(float)j / 32.0f);
        float ang = (float)l * inv;
        float s, c;
        sincosf(ang, &s, &c);
        g_cos[idx] = c;
        g_sin[idx] = s;
        return;
    }
    if (bid < 4352) {
        const float* src;
        __half* dst;
        int i;
        if (bid < 3328) { src = wq; dst = g_wqf; i = ((bid - 256) * 256 + t) * 4; }
        else            { src = ow; dst = g_owf; i = ((bid - 3328) * 256 + t) * 4; }
        float4 v = *(const float4*)&src[i];
        __half2 a = __floats2half2_rn(v.x, v.y);
        __half2 b = __floats2half2_rn(v.z, v.w);
        uint2 u;
        u.x = *(uint32_t*)&a;
        u.y = *(uint32_t*)&b;
        *(uint2*)&dst[i] = u;
        return;
    }
    // ---- ln1 ----
    int n = bid - 4352;
    const float* xr = x + (size_t)n * D_;
    float4 v = *(const float4*)&xr[t * 4];
    float s  = v.x + v.y + v.z + v.w;
    float s2 = v.x*v.x + v.y*v.y + v.z*v.z + v.w*v.w;
    #pragma unroll
    for (int o = 16; o >= 1; o >>= 1) {
        s  += __shfl_xor_sync(0xffffffffu, s,  o);
        s2 += __shfl_xor_sync(0xffffffffu, s2, o);
    }
    __shared__ float red[2][8];
    int lane = t & 31, wp = t >> 5;
    if (lane == 0) { red[0][wp] = s; red[1][wp] = s2; }
    __syncthreads();
    __shared__ float stat[2];
    if (t == 0) {
        float a = 0.f, c = 0.f;
        #pragma unroll
        for (int i = 0; i < 8; i++) { a += red[0][i]; c += red[1][i]; }
        float mu  = a * (1.0f / D_);
        float var = c * (1.0f / D_) - mu * mu;
        stat[0] = mu;
        stat[1] = rsqrtf(var + EPS);
    }
    __syncthreads();
    float mu = stat[0], rs = stat[1];
    float4 wv = *(const float4*)&ln1w[t * 4];
    float4 bv = *(const float4*)&ln1b[t * 4];
    float o0 = (v.x - mu) * rs * wv.x + bv.x;
    float o1 = (v.y - mu) * rs * wv.y + bv.y;
    float o2 = (v.z - mu) * rs * wv.z + bv.z;
    float o3 = (v.w - mu) * rs * wv.w + bv.w;
    __half2 a = __floats2half2_rn(o0, o1);
    __half2 bb = __floats2half2_rn(o2, o3);
    uint2 u;
    u.x = *(uint32_t*)&a;
    u.y = *(uint32_t*)&bb;
    *(uint2*)&g_hf[(size_t)n * D_ + t * 4] = u;
}

// ============ warp-MMA fp16 GEMM: C[M,N] = A[M,K]*B[N,K]^T (fp32 accum) ============
// CTA 128x128, 8 warps of 64x32. K64 pairs over 6-stage (3 pair-slot) ring.
// One __syncthreads per 64 warp-MMAs. MMA order identical to R10.
#define GSUB   (128 * 16)                 // fp16 elems per K16 sub-buffer
#define GCH    (2 * GSUB)                 // elems per K32 chunk (4096)
#define GMAT   (6 * GCH)                  // elems per matrix (6 stages)
#define GEMM_SMEM_BYTES (2 * GMAT * 2)    // 98304 B

__global__ __launch_bounds__(256) void gemm_f16(
    const __half* __restrict__ Af, const __half* __restrict__ Bf,
    float* __restrict__ C, int M, int N, int K)
{
    extern __shared__ __half smg[];
    __half* sA = smg;
    __half* sB = smg + GMAT;

    int tid = threadIdx.x;
    int warp = tid >> 5, lane = tid & 31;
    int m0 = blockIdx.y * 128, n0 = blockIdx.x * 128;
    int wm = (warp & 1) * 64, wn = (warp >> 1) * 32;

    int lrow = tid >> 1;
    int lch  = (tid & 1) * 8;
    uint32_t uA = smem_u32(sA), uB = smem_u32(sB);
    uint32_t dsto = (uint32_t)(lrow * 16 + lch) * 2;    // within a sub buffer

    const __half* gA = Af + (size_t)(m0 + lrow) * K + lch;
    const __half* gB = Bf + (size_t)(n0 + lrow) * K + lch;

    float d[4][4][4];
    #pragma unroll
    for (int mi = 0; mi < 4; mi++)
        #pragma unroll
        for (int ni = 0; ni < 4; ni++)
            #pragma unroll
            for (int r = 0; r < 4; r++) d[mi][ni][r] = 0.f;

    const int npair = K >> 6;           // K64 pairs (K=1024 -> 16)

    // chunk c -> smem elem offset: pair slot (c>>1)%3, chunk-in-pair c&1
    #define CHUNK_OFF(c) ((uint32_t)((((c) >> 1) % 3) * 2 + ((c) & 1)) * GCH)

    // prologue: pairs 0,1 (chunks 0..3), one commit per pair
    #pragma unroll
    for (int c = 0; c < 4; c++) {
        #pragma unroll
        for (int sub = 0; sub < 2; sub++) {
            uint32_t so = (CHUNK_OFF(c) + (uint32_t)(sub * GSUB)) * 2 + dsto;
            CP_ASYNC16(uA + so, gA + c * 32 + sub * 16);
            CP_ASYNC16(uB + so, gB + c * 32 + sub * 16);
        }
        if (c & 1) CP_COMMIT();
    }

    int ar = wm + (lane >> 2);
    int ac = (lane & 3) * 2;
    int br = wn + (lane >> 2);
    int bc = (lane & 3) * 2;

    for (int p = 0; p < npair; p++) {
        if (p == npair - 1) { CP_WAIT0(); } else { CP_WAIT1(); }
        __syncthreads();

        // prefetch pair p+2 into its slot (disjoint from slots p, p+1)
        if (p + 2 < npair) {
            #pragma unroll
            for (int ch = 0; ch < 2; ch++) {
                int c = 2 * (p + 2) + ch;
                #pragma unroll
                for (int sub = 0; sub < 2; sub++) {
                    uint32_t so = (CHUNK_OFF(c) + (uint32_t)(sub * GSUB)) * 2 + dsto;
                    CP_ASYNC16(uA + so, gA + c * 32 + sub * 16);
                    CP_ASYNC16(uB + so, gB + c * 32 + sub * 16);
                }
            }
        }
        CP_COMMIT();

        #pragma unroll
        for (int ch = 0; ch < 2; ch++) {
            int c = 2 * p + ch;
            #pragma unroll
            for (int sub = 0; sub < 2; sub++) {
                const __half* pA = sA + CHUNK_OFF(c) + sub * GSUB;
                const __half* pB = sB + CHUNK_OFF(c) + sub * GSUB;

                uint32_t ah[4][4], bh[4][2];
                #pragma unroll
                for (int mi = 0; mi < 4; mi++) {
                    int r0 = (ar + mi * 16) * 16 + ac;
                    int r1 = r0 + 8 * 16;
                    ah[mi][0] = *(const uint32_t*)(pA + r0);
                    ah[mi][1] = *(const uint32_t*)(pA + r1);
                    ah[mi][2] = *(const uint32_t*)(pA + r0 + 8);
                    ah[mi][3] = *(const uint32_t*)(pA + r1 + 8);
                }
                #pragma unroll
                for (int ni = 0; ni < 4; ni++) {
                    int c0 = (br + ni * 8) * 16 + bc;
                    bh[ni][0] = *(const uint32_t*)(pB + c0);
                    bh[ni][1] = *(const uint32_t*)(pB + c0 + 8);
                }

                #pragma unroll
                for (int mi = 0; mi < 4; mi++)
                    #pragma unroll
                    for (int ni = 0; ni < 4; ni++)
                        MMAF16(d[mi][ni], ah[mi], bh[ni]);
            }
        }
    }

    #pragma unroll
    for (int mi = 0; mi < 4; mi++) {
        int r = m0 + wm + mi * 16 + (lane >> 2);
        #pragma unroll
        for (int ni = 0; ni < 4; ni++) {
            int c = n0 + wn + ni * 8 + (lane & 3) * 2;
            *(float2*)&C[(size_t)r * N + c] = make_float2(d[mi][ni][0], d[mi][ni][1]);
            *(float2*)&C[(size_t)(r + 8) * N + c] = make_float2(d[mi][ni][2], d[mi][ni][3]);
        }
    }
}

// ---------- fused QK-LN+RoPE (blocks [0,4096)) + V transpose ([4096,6144)) ----------
__global__ void qkrope_vt_kernel(const float* __restrict__ qw,
                                 const float* __restrict__ kw,
                                 const int* __restrict__ seq_id_unused) {
    int bid = blockIdx.x;
    int t = threadIdx.x;

    if (bid >= 4096) {
        // ---- V transpose: g_qkv v-part -> [BH,DH,L] bf16 hi/lo ----
        __shared__ float tile[64][33];
        int bid2 = bid - 4096;
        int bh = bid2 >> 6;                 // 0..31
        int b = bh >> 4, h = bh & 15;
        int l0 = (bid2 & 63) * 32;
        int tx = t & 31, ty = t >> 5;
        #pragma unroll
        for (int i = 0; i < 4; i++) {
            int l = l0 + ty + i * 8;
            const float* row = g_qkv + (size_t)(b * L_ + l) * D3 + 2 * D_ + h * DH;
            tile[tx][ty + i * 8]      = row[tx];
            tile[tx + 32][ty + i * 8] = row[tx + 32];
        }
        __syncthreads();
        #pragma unroll
        for (int i = 0; i < 8; i++) {
            int d = ty + i * 8;
            float v = tile[d][tx];
            __nv_bfloat16 hb = __float2bfloat16(v);
            __nv_bfloat16 lb = __float2bfloat16(v - __bfloat162float(hb));
            size_t o = (size_t)(bh * DH + d) * L_ + l0 + tx;
            g_vth[o] = hb;
            g_vtl[o] = lb;
        }
        return;
    }

    // ---- QK-LN + RoPE ----
    int n = bid;
    int b = n >> 11;
    int l = n & 2047;
    const float* q = g_qkv + (size_t)n * D3;
    const float* k = q + D_;

    float4 qv = *(const float4*)&q[t * 4];
    float4 kv = *(const float4*)&k[t * 4];
    float qs  = qv.x + qv.y + qv.z + qv.w;
    float qs2 = qv.x*qv.x + qv.y*qv.y + qv.z*qv.z + qv.w*qv.w;
    float ks  = kv.x + kv.y + kv.z + kv.w;
    float ks2 = kv.x*kv.x + kv.y*kv.y + kv.z*kv.z + kv.w*kv.w;
    #pragma unroll
    for (int o = 16; o >= 1; o >>= 1) {
        qs  += __shfl_xor_sync(0xffffffffu, qs,  o);
        qs2 += __shfl_xor_sync(0xffffffffu, qs2, o);
        ks  += __shfl_xor_sync(0xffffffffu, ks,  o);
        ks2 += __shfl_xor_sync(0xffffffffu, ks2, o);
    }
    __shared__ float red[4][8];
    __shared__ float stat[4];
    int lane = t & 31, wp = t >> 5;
    if (lane == 0) { red[0][wp]=qs; red[1][wp]=qs2; red[2][wp]=ks; red[3][wp]=ks2; }
    __syncthreads();
    if (t == 0) {
        float a=0,c=0,e=0,f=0;
        #pragma unroll
        for (int i=0;i<8;i++){a+=red[0][i];c+=red[1][i];e+=red[2][i];f+=red[3][i];}
        float qmu=a*(1.f/D_), qvr=c*(1.f/D_)-qmu*qmu;
        float kmu=e*(1.f/D_), kvr=f*(1.f/D_)-kmu*kmu;
        stat[0]=qmu; stat[1]=rsqrtf(qvr+EPS);
        stat[2]=kmu; stat[3]=rsqrtf(kvr+EPS);
    }
    __syncthreads();
    float qmu=stat[0], qrs=stat[1], kmu=stat[2], krs=stat[3];
    float4 qwv = *(const float4*)&qw[t*4];
    float4 kwv = *(const float4*)&kw[t*4];
    float qnv[4], knv[4];
    qnv[0]=(qv.x-qmu)*qrs*qwv.x; qnv[1]=(qv.y-qmu)*qrs*qwv.y;
    qnv[2]=(qv.z-qmu)*qrs*qwv.z; qnv[3]=(qv.w-qmu)*qrs*qwv.w;
    knv[0]=(kv.x-kmu)*krs*kwv.x; knv[1]=(kv.y-kmu)*krs*kwv.y;
    knv[2]=(kv.z-kmu)*krs*kwv.z; knv[3]=(kv.w-kmu)*krs*kwv.w;

    // RoPE partner (d +/- 32) lives exactly 8 lanes away in the same warp
    float qp[4], kp[4];
    #pragma unroll
    for (int ii = 0; ii < 4; ii++) {
        qp[ii] = __shfl_xor_sync(0xffffffffu, qnv[ii], 8);
        kp[ii] = __shfl_xor_sync(0xffffffffu, knv[ii], 8);
    }
    bool hiHalf = (t & 8) != 0;     // j0 >= 32
    int d0 = t * 4;
    int hh = d0 >> 6;
    int j0 = d0 & 63;
    int f0 = d0 & 31;
    float qo[4], ko[4];
    #pragma unroll
    for (int ii = 0; ii < 4; ii++) {
        float c = g_cos[l * 32 + f0 + ii];
        float s = g_sin[l * 32 + f0 + ii];
        if (!hiHalf) {
            qo[ii] = qnv[ii] * c - qp[ii] * s;
            ko[ii] = knv[ii] * c - kp[ii] * s;
        } else {
            qo[ii] = qnv[ii] * c + qp[ii] * s;
            ko[ii] = knv[ii] * c + kp[ii] * s;
        }
        qo[ii] *= 0.125f;   // fold softmax scale into q
    }
    size_t oidx = (((size_t)(b * H_ + hh)) * L_ + l) * DH + j0;
    union { __nv_bfloat16 h[4]; uint2 u; } uqh, uql, ukh, ukl;
    #pragma unroll
    for (int ii = 0; ii < 4; ii++) {
        __nv_bfloat16 hb = __float2bfloat16(qo[ii]);
        uqh.h[ii] = hb;
        uql.h[ii] = __float2bfloat16(qo[ii] - __bfloat162float(hb));
        __nv_bfloat16 kb = __float2bfloat16(ko[ii]);
        ukh.h[ii] = kb;
        ukl.h[ii] = __float2bfloat16(ko[ii] - __bfloat162float(kb));
    }
    *(uint2*)&g_qh[oidx] = uqh.u;
    *(uint2*)&g_ql[oidx] = uql.u;
    *(uint2*)&g_kh[oidx] = ukh.u;
    *(uint2*)&g_kl[oidx] = ukl.u;
}

// ---------------- flash attention on mma.sync (bf16 split-3) ----------------
// Block-diagonal mask: seq_id sorted -> valid k-tiles form a contiguous range.
#define KPAD 72
#define AT_SM_QH 0
#define AT_SM_QL 9216
#define AT_SM_KV 18432
#define AT_SM_TILE 9216
#define AT_SM_BUF 36864
#define AT_SM_SK (18432 + 2 * 36864)
#define ATT2_SMEM (AT_SM_SK + 512)

__global__ __launch_bounds__(128) void attn_mma(const int* __restrict__ seq_id) {
    extern __shared__ char sm[];
    const uint32_t sbase = smem_u32(sm);
    int tid = threadIdx.x, lane = tid & 31, w = tid >> 5;
    int qt = blockIdx.x, h = blockIdx.y, b = blockIdx.z;
    int bh = b * H_ + h;
    int row0 = qt * 64;

    const __nv_bfloat16* gQh = g_qh + ((size_t)bh * L_ + row0) * DH;
    const __nv_bfloat16* gQl = g_ql + ((size_t)bh * L_ + row0) * DH;
    const __nv_bfloat16* gKh = g_kh + (size_t)bh * L_ * DH;
    const __nv_bfloat16* gKl = g_kl + (size_t)bh * L_ * DH;
    const __nv_bfloat16* gVh = g_vth + (size_t)bh * DH * L_;
    const __nv_bfloat16* gVl = g_vtl + (size_t)bh * DH * L_;

    // ---- valid k-tile range (contiguous because seq_id is sorted) ----
    int q_lo = seq_id[b * L_ + row0];
    int q_hi = seq_id[b * L_ + row0 + 63];
    unsigned vmask;
    {
        int klo = seq_id[b * L_ + lane * 64];
        int khi = seq_id[b * L_ + lane * 64 + 63];
        bool ok = (khi >= q_lo) && (klo <= q_hi);
        vmask = __ballot_sync(0xffffffffu, ok);
    }
    int tlo = __ffs(vmask) - 1;
    int thi = 31 - __clz(vmask);

    int lrow = tid >> 1;          // 0..63
    int cb0  = (tid & 1) * 4;     // chunk base (16B chunks)

    // ---- prologue: Q tiles ----
    #pragma unroll
    for (int c = 0; c < 4; c++) {
        int ch = cb0 + c;
        uint32_t so = (uint32_t)(lrow * KPAD + ch * 8) * 2;
        CP_ASYNC16(sbase + AT_SM_QH + so, gQh + lrow * DH + ch * 8);
        CP_ASYNC16(sbase + AT_SM_QL + so, gQl + lrow * DH + ch * 8);
    }
    CP_COMMIT();
    // ---- K/V tile tlo ----
    {
        int col0 = tlo * 64;
        uint32_t dst = sbase + AT_SM_KV;
        #pragma unroll
        for (int c = 0; c < 4; c++) {
            int ch = cb0 + c;
            uint32_t so = (uint32_t)(lrow * KPAD + ch * 8) * 2;
            CP_ASYNC16(dst + so,                  gKh + (size_t)(col0 + lrow) * DH + ch * 8);
            CP_ASYNC16(dst + AT_SM_TILE + so,     gKl + (size_t)(col0 + lrow) * DH + ch * 8);
            CP_ASYNC16(dst + 2 * AT_SM_TILE + so, gVh + (size_t)lrow * L_ + col0 + ch * 8);
            CP_ASYNC16(dst + 3 * AT_SM_TILE + so, gVl + (size_t)lrow * L_ + col0 + ch * 8);
        }
    }
    CP_COMMIT();
    if (tid < 64) ((int*)(sm + AT_SM_SK))[tid] = seq_id[b * L_ + tlo * 64 + tid];
    int sq0 = seq_id[b * L_ + row0 + w * 16 + (lane >> 2)];
    int sq1 = seq_id[b * L_ + row0 + w * 16 + (lane >> 2) + 8];

    CP_WAIT1();
    __syncthreads();

    // ---- extract Q fragments (held for whole kernel) ----
    uint32_t qfh[4][4], qfl[4][4];
    {
        const __nv_bfloat16* sQh = (const __nv_bfloat16*)(sm + AT_SM_QH);
        const __nv_bfloat16* sQl = (const __nv_bfloat16*)(sm + AT_SM_QL);
        #pragma unroll
        for (int s = 0; s < 4; s++) {
            int base = (w * 16 + (lane >> 2)) * KPAD + s * 16 + (lane & 3) * 2;
            qfh[s][0] = *(const uint32_t*)(sQh + base);
            qfh[s][1] = *(const uint32_t*)(sQh + base + 8 * KPAD);
            qfh[s][2] = *(const uint32_t*)(sQh + base + 8);
            qfh[s][3] = *(const uint32_t*)(sQh + base + 8 * KPAD + 8);
            qfl[s][0] = *(const uint32_t*)(sQl + base);
            qfl[s][1] = *(const uint32_t*)(sQl + base + 8 * KPAD);
            qfl[s][2] = *(const uint32_t*)(sQl + base + 8);
            qfl[s][3] = *(const uint32_t*)(sQl + base + 8 * KPAD + 8);
        }
    }

    float m0 = -1e30f, m1 = -1e30f, l0 = 0.f, l1 = 0.f;
    float pv[8][4];
    #pragma unroll
    for (int j = 0; j < 8; j++)
        #pragma unroll
        for (int r = 0; r < 4; r++) pv[j][r] = 0.f;

    for (int it = tlo; it <= thi; it++) {
        int buf = (it - tlo) & 1;
        CP_WAIT0();
        __syncthreads();

        // prefetch next tile into other buffer
        if (it + 1 <= thi) {
            int col0n = (it + 1) * 64;
            uint32_t dst = sbase + AT_SM_KV + (buf ^ 1) * AT_SM_BUF;
            #pragma unroll
            for (int c = 0; c < 4; c++) {
                int ch = cb0 + c;
                uint32_t so = (uint32_t)(lrow * KPAD + ch * 8) * 2;
                CP_ASYNC16(dst + so,                  gKh + (size_t)(col0n + lrow) * DH + ch * 8);
                CP_ASYNC16(dst + AT_SM_TILE + so,     gKl + (size_t)(col0n + lrow) * DH + ch * 8);
                CP_ASYNC16(dst + 2 * AT_SM_TILE + so, gVh + (size_t)lrow * L_ + col0n + ch * 8);
                CP_ASYNC16(dst + 3 * AT_SM_TILE + so, gVl + (size_t)lrow * L_ + col0n + ch * 8);
            }
            if (tid < 64)
                ((int*)(sm + AT_SM_SK))[(buf ^ 1) * 64 + tid] =
                    seq_id[b * L_ + col0n + tid];
        }
        CP_COMMIT();

        const __nv_bfloat16* sKh = (const __nv_bfloat16*)(sm + AT_SM_KV + buf * AT_SM_BUF);
        const __nv_bfloat16* sKl = sKh + 4608;
        const __nv_bfloat16* sVh = sKh + 9216;
        const __nv_bfloat16* sVl = sKh + 13824;
        const int* skp = (const int*)(sm + AT_SM_SK) + buf * 64;

        // ---- S = Q K^T (split-3) ----
        float sf[8][4];
        #pragma unroll
        for (int j = 0; j < 8; j++)
            #pragma unroll
            for (int r = 0; r < 4; r++) sf[j][r] = 0.f;
        #pragma unroll
        for (int s = 0; s < 4; s++) {
            #pragma unroll
            for (int j = 0; j < 8; j++) {
                int off = (j * 8 + (lane >> 2)) * KPAD + s * 16 + (lane & 3) * 2;
                uint32_t bhf[2] = {*(const uint32_t*)(sKh + off),
                                   *(const uint32_t*)(sKh + off + 8)};
                uint32_t blf[2] = {*(const uint32_t*)(sKl + off),
                                   *(const uint32_t*)(sKl + off + 8)};
                MMA16816(sf[j], qfh[s], bhf);
                MMA16816(sf[j], qfh[s], blf);
                MMA16816(sf[j], qfl[s], bhf);
            }
        }

        // ---- mask + online softmax (c-frag layout) ----
        int colb = (lane & 3) * 2;
        float nm0 = m0, nm1 = m1;
        #pragma unroll
        for (int j = 0; j < 8; j++) {
            int k0 = skp[8 * j + colb], k1 = skp[8 * j + colb + 1];
            sf[j][0] = (k0 == sq0) ? sf[j][0] : -2e30f;
            sf[j][1] = (k1 == sq0) ? sf[j][1] : -2e30f;
            sf[j][2] = (k0 == sq1) ? sf[j][2] : -2e30f;
            sf[j][3] = (k1 == sq1) ? sf[j][3] : -2e30f;
            nm0 = fmaxf(nm0, fmaxf(sf[j][0], sf[j][1]));
            nm1 = fmaxf(nm1, fmaxf(sf[j][2], sf[j][3]));
        }
        nm0 = fmaxf(nm0, __shfl_xor_sync(0xffffffffu, nm0, 1));
        nm0 = fmaxf(nm0, __shfl_xor_sync(0xffffffffu, nm0, 2));
        nm1 = fmaxf(nm1, __shfl_xor_sync(0xffffffffu, nm1, 1));
        nm1 = fmaxf(nm1, __shfl_xor_sync(0xffffffffu, nm1, 2));
        float a0 = __expf(m0 - nm0), a1 = __expf(m1 - nm1);
        m0 = nm0; m1 = nm1;

        float s0 = 0.f, s1 = 0.f;
        uint32_t ph[4][4], pl[4][4];
        #pragma unroll
        for (int j = 0; j < 8; j++) {
            float p0 = __expf(sf[j][0] - m0), p1 = __expf(sf[j][1] - m0);
            float p2 = __expf(sf[j][2] - m1), p3 = __expf(sf[j][3] - m1);
            s0 += p0 + p1; s1 += p2 + p3;
            __nv_bfloat162 h01 = __float22bfloat162_rn(make_float2(p0, p1));
            float2 f01 = __bfloat1622float2(h01);
            __nv_bfloat162 l01 = __float22bfloat162_rn(make_float2(p0 - f01.x, p1 - f01.y));
            __nv_bfloat162 h23 = __float22bfloat162_rn(make_float2(p2, p3));
            float2 f23 = __bfloat1622float2(h23);
            __nv_bfloat162 l23 = __float22bfloat162_rn(make_float2(p2 - f23.x, p3 - f23.y));
            int s_ = j >> 1;
            int o  = (j & 1) * 2;
            ph[s_][o]     = *(uint32_t*)&h01;
            ph[s_][o + 1] = *(uint32_t*)&h23;
            pl[s_][o]     = *(uint32_t*)&l01;
            pl[s_][o + 1] = *(uint32_t*)&l23;
        }
        s0 += __shfl_xor_sync(0xffffffffu, s0, 1);
        s0 += __shfl_xor_sync(0xffffffffu, s0, 2);
        s1 += __shfl_xor_sync(0xffffffffu, s1, 1);
        s1 += __shfl_xor_sync(0xffffffffu, s1, 2);
        l0 = l0 * a0 + s0;
        l1 = l1 * a1 + s1;
        #pragma unroll
        for (int j = 0; j < 8; j++) {
            pv[j][0] *= a0; pv[j][1] *= a0; pv[j][2] *= a1; pv[j][3] *= a1;
        }

        // ---- PV (split-3), B = Vt[dh][c] ----
        #pragma unroll
        for (int s = 0; s < 4; s++) {
            #pragma unroll
            for (int j = 0; j < 8; j++) {
                int off = (j * 8 + (lane >> 2)) * KPAD + s * 16 + (lane & 3) * 2;
                uint32_t bhf[2] = {*(const uint32_t*)(sVh + off),
                                   *(const uint32_t*)(sVh + off + 8)};
                uint32_t blf[2] = {*(const uint32_t*)(sVl + off),
                                   *(const uint32_t*)(sVl + off + 8)};
                MMA16816(pv[j], ph[s], bhf);
                MMA16816(pv[j], ph[s], blf);
                MMA16816(pv[j], pl[s], bhf);
            }
        }
    }

    // ---- epilogue: ctx / l -> fp16 [B,L,H,DH] ----
    float inv0 = 1.0f / l0, inv1 = 1.0f / l1;
    int r0g = row0 + w * 16 + (lane >> 2);
    #pragma unroll
    for (int j = 0; j < 8; j++) {
        int c = 8 * j + (lane & 3) * 2;
        size_t o0 = (((size_t)b * L_ + r0g) * H_ + h) * DH + c;
        size_t o1 = (((size_t)b * L_ + r0g + 8) * H_ + h) * DH + c;
        __half2 hx = __floats2half2_rn(pv[j][0] * inv0, pv[j][1] * inv0);
        __half2 hy = __floats2half2_rn(pv[j][2] * inv1, pv[j][3] * inv1);
        *(uint32_t*)&g_cf[o0] = *(uint32_t*)&hx;
        *(uint32_t*)&g_cf[o1] = *(uint32_t*)&hy;
    }
}

// ---------------- launch ----------------
extern "C" void kernel_launch(void* const* d_in, const int* in_sizes, int n_in,
                              void* d_out, int out_size) {
    const float* x      = (const float*)d_in[0];
    const int*   seq_id = (const int*)  d_in[1];
    const float* ln1_w  = (const float*)d_in[2];
    const float* ln1_b  = (const float*)d_in[3];
    const float* w_qkv  = (const float*)d_in[4];
    const float* q_ln_w = (const float*)d_in[5];
    const float* k_ln_w = (const float*)d_in[6];
    const float* out_w  = (const float*)d_in[7];
    float* out = (float*)d_out;

    void *phf, *pwqf, *powf, *pcf, *pqkv;
    cudaGetSymbolAddress(&phf,  g_hf);
    cudaGetSymbolAddress(&pwqf, g_wqf);
    cudaGetSymbolAddress(&powf, g_owf);
    cudaGetSymbolAddress(&pcf,  g_cf);
    cudaGetSymbolAddress(&pqkv, g_qkv);

    cudaFuncSetAttribute(attn_mma, cudaFuncAttributeMaxDynamicSharedMemorySize,
                         ATT2_SMEM);
    cudaFuncSetAttribute(gemm_f16, cudaFuncAttributeMaxDynamicSharedMemorySize,
                         GEMM_SMEM_BYTES);

    prep_kernel<<<8448, 256>>>(x, ln1_w, ln1_b, w_qkv, out_w);
    gemm_f16<<<dim3(D3 / 128, NT / 128), 256, GEMM_SMEM_BYTES>>>(
        (const __half*)phf, (const __half*)pwqf, (float*)pqkv, NT, D3, D_);
    qkrope_vt_kernel<<<6144, 256>>>(q_ln_w, k_ln_w, seq_id);
    attn_mma<<<dim3(L_ / 64, H_, B_), 128, ATT2_SMEM>>>(seq_id);
    gemm_f16<<<dim3(D_ / 128, NT / 128), 256, GEMM_SMEM_BYTES>>>(
        (const __half*)pcf, (const __half*)powf, out, NT, D_, D_);
}

// round 12
// speedup vs baseline: 3.7812x; 1.2181x over previous
#include <cuda_runtime.h>
#include <cuda_bf16.h>
#include <cuda_fp16.h>
#include <cstdint>
#include <math.h>

// Problem constants
#define B_  2
#define L_  2048
#define NT  4096            // B*L tokens
#define D_  1024
#define H_  16
#define DH  64
#define D3  3072
#define EPS 1e-5f

// ---------------- scratch (device globals; no allocation) ----------------
__device__ __half g_hf[NT * D_];          // LN1 out (fp16)
__device__ __half g_wqf[D3 * D_];         // w_qkv (fp16)
__device__ __half g_owf[D_ * D_];         // out_w (fp16)
__device__ __half g_cf[NT * D_];          // ctx (fp16) [B,L,H,DH] == [NT,D]
__device__ __half g_qf[NT * D_];          // q (scaled, fp16) [BH,L,DH]
__device__ __half g_kf[NT * D_];          // k (fp16) [BH,L,DH]
__device__ __half g_vtf[NT * D_];         // v^T (fp16) [BH,DH,L]
__device__ float g_qkv[NT * D3];          // QKV gemm output [NT, 3D]
__device__ float g_cos[L_ * 32];
__device__ float g_sin[L_ * 32];

// ---------------- helpers ----------------
__device__ __forceinline__ uint32_t smem_u32(const void* p) {
    uint32_t a;
    asm("{ .reg .u64 t; cvta.to.shared.u64 t, %1; cvt.u32.u64 %0, t; }"
        : "=r"(a) : "l"(p));
    return a;
}
#define CP_ASYNC16(dst, src) \
    asm volatile("cp.async.cg.shared.global [%0], [%1], 16;" :: "r"(dst), "l"(src))
#define CP_COMMIT() asm volatile("cp.async.commit_group;" ::: "memory")
#define CP_WAIT0()  asm volatile("cp.async.wait_group 0;" ::: "memory")
#define CP_WAIT1()  asm volatile("cp.async.wait_group 1;" ::: "memory")

// fp16 mma
#define MMAF16(d, a, b) \
    asm volatile( \
        "mma.sync.aligned.m16n8k16.row.col.f32.f16.f16.f32 " \
        "{%0,%1,%2,%3}, {%4,%5,%6,%7}, {%8,%9}, {%0,%1,%2,%3};" \
        : "+f"((d)[0]), "+f"((d)[1]), "+f"((d)[2]), "+f"((d)[3]) \
        : "r"((a)[0]), "r"((a)[1]), "r"((a)[2]), "r"((a)[3]), \
          "r"((b)[0]), "r"((b)[1]))

// ---------------- fused prep: rope table + weight conv + LN1 ----------------
// grid: [0,256) rope | [256,3328) conv w_qkv | [3328,4352) conv out_w |
//       [4352,8448) ln1
__global__ void prep_kernel(const float* __restrict__ x,
                            const float* __restrict__ ln1w,
                            const float* __restrict__ ln1b,
                            const float* __restrict__ wq,
                            const float* __restrict__ ow) {
    int bid = blockIdx.x;
    int t = threadIdx.x;
    if (bid < 256) {
        int idx = bid * 256 + t;
        int l = idx >> 5;
        int j = idx & 31;
        float inv = powf(10000.0f, -(float)j / 32.0f);
        float ang = (float)l * inv;
        float s, c;
        sincosf(ang, &s, &c);
        g_cos[idx] = c;
        g_sin[idx] = s;
        return;
    }
    if (bid < 4352) {
        const float* src;
        __half* dst;
        int i;
        if (bid < 3328) { src = wq; dst = g_wqf; i = ((bid - 256) * 256 + t) * 4; }
        else            { src = ow; dst = g_owf; i = ((bid - 3328) * 256 + t) * 4; }
        float4 v = *(const float4*)&src[i];
        __half2 a = __floats2half2_rn(v.x, v.y);
        __half2 b = __floats2half2_rn(v.z, v.w);
        uint2 u;
        u.x = *(uint32_t*)&a;
        u.y = *(uint32_t*)&b;
        *(uint2*)&dst[i] = u;
        return;
    }
    // ---- ln1 ----
    int n = bid - 4352;
    const float* xr = x + (size_t)n * D_;
    float4 v = *(const float4*)&xr[t * 4];
    float s  = v.x + v.y + v.z + v.w;
    float s2 = v.x*v.x + v.y*v.y + v.z*v.z + v.w*v.w;
    #pragma unroll
    for (int o = 16; o >= 1; o >>= 1) {
        s  += __shfl_xor_sync(0xffffffffu, s,  o);
        s2 += __shfl_xor_sync(0xffffffffu, s2, o);
    }
    __shared__ float red[2][8];
    int lane = t & 31, wp = t >> 5;
    if (lane == 0) { red[0][wp] = s; red[1][wp] = s2; }
    __syncthreads();
    __shared__ float stat[2];
    if (t == 0) {
        float a = 0.f, c = 0.f;
        #pragma unroll
        for (int i = 0; i < 8; i++) { a += red[0][i]; c += red[1][i]; }
        float mu  = a * (1.0f / D_);
        float var = c * (1.0f / D_) - mu * mu;
        stat[0] = mu;
        stat[1] = rsqrtf(var + EPS);
    }
    __syncthreads();
    float mu = stat[0], rs = stat[1];
    float4 wv = *(const float4*)&ln1w[t * 4];
    float4 bv = *(const float4*)&ln1b[t * 4];
    float o0 = (v.x - mu) * rs * wv.x + bv.x;
    float o1 = (v.y - mu) * rs * wv.y + bv.y;
    float o2 = (v.z - mu) * rs * wv.z + bv.z;
    float o3 = (v.w - mu) * rs * wv.w + bv.w;
    __half2 a = __floats2half2_rn(o0, o1);
    __half2 bb = __floats2half2_rn(o2, o3);
    uint2 u;
    u.x = *(uint32_t*)&a;
    u.y = *(uint32_t*)&bb;
    *(uint2*)&g_hf[(size_t)n * D_ + t * 4] = u;
}

// ============ warp-MMA fp16 GEMM: C[M,N] = A[M,K]*B[N,K]^T (fp32 accum) ============
// CTA 128x128, 8 warps of 64x32. K64 pairs over 6-stage (3 pair-slot) ring.
#define GSUB   (128 * 16)                 // fp16 elems per K16 sub-buffer
#define GCH    (2 * GSUB)                 // elems per K32 chunk (4096)
#define GMAT   (6 * GCH)                  // elems per matrix (6 stages)
#define GEMM_SMEM_BYTES (2 * GMAT * 2)    // 98304 B

__global__ __launch_bounds__(256) void gemm_f16(
    const __half* __restrict__ Af, const __half* __restrict__ Bf,
    float* __restrict__ C, int M, int N, int K)
{
    extern __shared__ __half smg[];
    __half* sA = smg;
    __half* sB = smg + GMAT;

    int tid = threadIdx.x;
    int warp = tid >> 5, lane = tid & 31;
    int m0 = blockIdx.y * 128, n0 = blockIdx.x * 128;
    int wm = (warp & 1) * 64, wn = (warp >> 1) * 32;

    int lrow = tid >> 1;
    int lch  = (tid & 1) * 8;
    uint32_t uA = smem_u32(sA), uB = smem_u32(sB);
    uint32_t dsto = (uint32_t)(lrow * 16 + lch) * 2;    // within a sub buffer

    const __half* gA = Af + (size_t)(m0 + lrow) * K + lch;
    const __half* gB = Bf + (size_t)(n0 + lrow) * K + lch;

    float d[4][4][4];
    #pragma unroll
    for (int mi = 0; mi < 4; mi++)
        #pragma unroll
        for (int ni = 0; ni < 4; ni++)
            #pragma unroll
            for (int r = 0; r < 4; r++) d[mi][ni][r] = 0.f;

    const int npair = K >> 6;           // K64 pairs (K=1024 -> 16)

    #define CHUNK_OFF(c) ((uint32_t)((((c) >> 1) % 3) * 2 + ((c) & 1)) * GCH)

    // prologue: pairs 0,1 (chunks 0..3), one commit per pair
    #pragma unroll
    for (int c = 0; c < 4; c++) {
        #pragma unroll
        for (int sub = 0; sub < 2; sub++) {
            uint32_t so = (CHUNK_OFF(c) + (uint32_t)(sub * GSUB)) * 2 + dsto;
            CP_ASYNC16(uA + so, gA + c * 32 + sub * 16);
            CP_ASYNC16(uB + so, gB + c * 32 + sub * 16);
        }
        if (c & 1) CP_COMMIT();
    }

    int ar = wm + (lane >> 2);
    int ac = (lane & 3) * 2;
    int br = wn + (lane >> 2);
    int bc = (lane & 3) * 2;

    for (int p = 0; p < npair; p++) {
        if (p == npair - 1) { CP_WAIT0(); } else { CP_WAIT1(); }
        __syncthreads();

        if (p + 2 < npair) {
            #pragma unroll
            for (int ch = 0; ch < 2; ch++) {
                int c = 2 * (p + 2) + ch;
                #pragma unroll
                for (int sub = 0; sub < 2; sub++) {
                    uint32_t so = (CHUNK_OFF(c) + (uint32_t)(sub * GSUB)) * 2 + dsto;
                    CP_ASYNC16(uA + so, gA + c * 32 + sub * 16);
                    CP_ASYNC16(uB + so, gB + c * 32 + sub * 16);
                }
            }
        }
        CP_COMMIT();

        #pragma unroll
        for (int ch = 0; ch < 2; ch++) {
            int c = 2 * p + ch;
            #pragma unroll
            for (int sub = 0; sub < 2; sub++) {
                const __half* pA = sA + CHUNK_OFF(c) + sub * GSUB;
                const __half* pB = sB + CHUNK_OFF(c) + sub * GSUB;

                uint32_t ah[4][4], bh[4][2];
                #pragma unroll
                for (int mi = 0; mi < 4; mi++) {
                    int r0 = (ar + mi * 16) * 16 + ac;
                    int r1 = r0 + 8 * 16;
                    ah[mi][0] = *(const uint32_t*)(pA + r0);
                    ah[mi][1] = *(const uint32_t*)(pA + r1);
                    ah[mi][2] = *(const uint32_t*)(pA + r0 + 8);
                    ah[mi][3] = *(const uint32_t*)(pA + r1 + 8);
                }
                #pragma unroll
                for (int ni = 0; ni < 4; ni++) {
                    int c0 = (br + ni * 8) * 16 + bc;
                    bh[ni][0] = *(const uint32_t*)(pB + c0);
                    bh[ni][1] = *(const uint32_t*)(pB + c0 + 8);
                }

                #pragma unroll
                for (int mi = 0; mi < 4; mi++)
                    #pragma unroll
                    for (int ni = 0; ni < 4; ni++)
                        MMAF16(d[mi][ni], ah[mi], bh[ni]);
            }
        }
    }

    #pragma unroll
    for (int mi = 0; mi < 4; mi++) {
        int r = m0 + wm + mi * 16 + (lane >> 2);
        #pragma unroll
        for (int ni = 0; ni < 4; ni++) {
            int c = n0 + wn + ni * 8 + (lane & 3) * 2;
            *(float2*)&C[(size_t)r * N + c] = make_float2(d[mi][ni][0], d[mi][ni][1]);
            *(float2*)&C[(size_t)(r + 8) * N + c] = make_float2(d[mi][ni][2], d[mi][ni][3]);
        }
    }
}

// ---------- fused QK-LN+RoPE (blocks [0,4096)) + V transpose ([4096,6144)) ----------
__global__ void qkrope_vt_kernel(const float* __restrict__ qw,
                                 const float* __restrict__ kw) {
    int bid = blockIdx.x;
    int t = threadIdx.x;

    if (bid >= 4096) {
        // ---- V transpose: g_qkv v-part -> [BH,DH,L] fp16 ----
        __shared__ float tile[64][33];
        int bid2 = bid - 4096;
        int bh = bid2 >> 6;                 // 0..31
        int b = bh >> 4, h = bh & 15;
        int l0 = (bid2 & 63) * 32;
        int tx = t & 31, ty = t >> 5;
        #pragma unroll
        for (int i = 0; i < 4; i++) {
            int l = l0 + ty + i * 8;
            const float* row = g_qkv + (size_t)(b * L_ + l) * D3 + 2 * D_ + h * DH;
            tile[tx][ty + i * 8]      = row[tx];
            tile[tx + 32][ty + i * 8] = row[tx + 32];
        }
        __syncthreads();
        #pragma unroll
        for (int i = 0; i < 8; i++) {
            int d = ty + i * 8;
            size_t o = (size_t)(bh * DH + d) * L_ + l0 + tx;
            g_vtf[o] = __float2half_rn(tile[d][tx]);
        }
        return;
    }

    // ---- QK-LN + RoPE ----
    int n = bid;
    int b = n >> 11;
    int l = n & 2047;
    const float* q = g_qkv + (size_t)n * D3;
    const float* k = q + D_;

    float4 qv = *(const float4*)&q[t * 4];
    float4 kv = *(const float4*)&k[t * 4];
    float qs  = qv.x + qv.y + qv.z + qv.w;
    float qs2 = qv.x*qv.x + qv.y*qv.y + qv.z*qv.z + qv.w*qv.w;
    float ks  = kv.x + kv.y + kv.z + kv.w;
    float ks2 = kv.x*kv.x + kv.y*kv.y + kv.z*kv.z + kv.w*kv.w;
    #pragma unroll
    for (int o = 16; o >= 1; o >>= 1) {
        qs  += __shfl_xor_sync(0xffffffffu, qs,  o);
        qs2 += __shfl_xor_sync(0xffffffffu, qs2, o);
        ks  += __shfl_xor_sync(0xffffffffu, ks,  o);
        ks2 += __shfl_xor_sync(0xffffffffu, ks2, o);
    }
    __shared__ float red[4][8];
    __shared__ float stat[4];
    int lane = t & 31, wp = t >> 5;
    if (lane == 0) { red[0][wp]=qs; red[1][wp]=qs2; red[2][wp]=ks; red[3][wp]=ks2; }
    __syncthreads();
    if (t == 0) {
        float a=0,c=0,e=0,f=0;
        #pragma unroll
        for (int i=0;i<8;i++){a+=red[0][i];c+=red[1][i];e+=red[2][i];f+=red[3][i];}
        float qmu=a*(1.f/D_), qvr=c*(1.f/D_)-qmu*qmu;
        float kmu=e*(1.f/D_), kvr=f*(1.f/D_)-kmu*kmu;
        stat[0]=qmu; stat[1]=rsqrtf(qvr+EPS);
        stat[2]=kmu; stat[3]=rsqrtf(kvr+EPS);
    }
    __syncthreads();
    float qmu=stat[0], qrs=stat[1], kmu=stat[2], krs=stat[3];
    float4 qwv = *(const float4*)&qw[t*4];
    float4 kwv = *(const float4*)&kw[t*4];
    float qnv[4], knv[4];
    qnv[0]=(qv.x-qmu)*qrs*qwv.x; qnv[1]=(qv.y-qmu)*qrs*qwv.y;
    qnv[2]=(qv.z-qmu)*qrs*qwv.z; qnv[3]=(qv.w-qmu)*qrs*qwv.w;
    knv[0]=(kv.x-kmu)*krs*kwv.x; knv[1]=(kv.y-kmu)*krs*kwv.y;
    knv[2]=(kv.z-kmu)*krs*kwv.z; knv[3]=(kv.w-kmu)*krs*kwv.w;

    // RoPE partner (d +/- 32) lives exactly 8 lanes away in the same warp
    float qp[4], kp[4];
    #pragma unroll
    for (int ii = 0; ii < 4; ii++) {
        qp[ii] = __shfl_xor_sync(0xffffffffu, qnv[ii], 8);
        kp[ii] = __shfl_xor_sync(0xffffffffu, knv[ii], 8);
    }
    bool hiHalf = (t & 8) != 0;     // j0 >= 32
    int d0 = t * 4;
    int hh = d0 >> 6;
    int j0 = d0 & 63;
    int f0 = d0 & 31;
    float qo[4], ko[4];
    #pragma unroll
    for (int ii = 0; ii < 4; ii++) {
        float c = g_cos[l * 32 + f0 + ii];
        float s = g_sin[l * 32 + f0 + ii];
        if (!hiHalf) {
            qo[ii] = qnv[ii] * c - qp[ii] * s;
            ko[ii] = knv[ii] * c - kp[ii] * s;
        } else {
            qo[ii] = qnv[ii] * c + qp[ii] * s;
            ko[ii] = knv[ii] * c + kp[ii] * s;
        }
        qo[ii] *= 0.125f;   // fold softmax scale into q
    }
    size_t oidx = (((size_t)(b * H_ + hh)) * L_ + l) * DH + j0;
    __half2 q01 = __floats2half2_rn(qo[0], qo[1]);
    __half2 q23 = __floats2half2_rn(qo[2], qo[3]);
    __half2 k01 = __floats2half2_rn(ko[0], ko[1]);
    __half2 k23 = __floats2half2_rn(ko[2], ko[3]);
    uint2 uq, uk;
    uq.x = *(uint32_t*)&q01; uq.y = *(uint32_t*)&q23;
    uk.x = *(uint32_t*)&k01; uk.y = *(uint32_t*)&k23;
    *(uint2*)&g_qf[oidx] = uq;
    *(uint2*)&g_kf[oidx] = uk;
}

// ---------------- flash attention on mma.sync (fp16 single-term) ----------------
// Block-diagonal mask: seq_id sorted -> valid k-tiles form a contiguous range.
#define KPAD 72
#define A2_Q    0
#define A2_KV   9216
#define A2_TILE 9216
#define A2_BUF  18432
#define A2_SK   (9216 + 2 * 18432)     // 46080
#define ATT3_SMEM (A2_SK + 512)

__global__ __launch_bounds__(128) void attn_mma(const int* __restrict__ seq_id) {
    extern __shared__ char sm[];
    const uint32_t sbase = smem_u32(sm);
    int tid = threadIdx.x, lane = tid & 31, w = tid >> 5;
    int qt = blockIdx.x, h = blockIdx.y, b = blockIdx.z;
    int bh = b * H_ + h;
    int row0 = qt * 64;

    const __half* gQf = g_qf + ((size_t)bh * L_ + row0) * DH;
    const __half* gKf = g_kf + (size_t)bh * L_ * DH;
    const __half* gVf = g_vtf + (size_t)bh * DH * L_;

    // ---- valid k-tile range (contiguous because seq_id is sorted) ----
    int q_lo = seq_id[b * L_ + row0];
    int q_hi = seq_id[b * L_ + row0 + 63];
    unsigned vmask;
    {
        int klo = seq_id[b * L_ + lane * 64];
        int khi = seq_id[b * L_ + lane * 64 + 63];
        bool ok = (khi >= q_lo) && (klo <= q_hi);
        vmask = __ballot_sync(0xffffffffu, ok);
    }
    int tlo = __ffs(vmask) - 1;
    int thi = 31 - __clz(vmask);

    int lrow = tid >> 1;          // 0..63
    int cb0  = (tid & 1) * 4;     // chunk base (16B chunks)

    // ---- prologue: Q tile ----
    #pragma unroll
    for (int c = 0; c < 4; c++) {
        int ch = cb0 + c;
        uint32_t so = (uint32_t)(lrow * KPAD + ch * 8) * 2;
        CP_ASYNC16(sbase + A2_Q + so, gQf + lrow * DH + ch * 8);
    }
    CP_COMMIT();
    // ---- K/V tile tlo ----
    {
        int col0 = tlo * 64;
        uint32_t dst = sbase + A2_KV;
        #pragma unroll
        for (int c = 0; c < 4; c++) {
            int ch = cb0 + c;
            uint32_t so = (uint32_t)(lrow * KPAD + ch * 8) * 2;
            CP_ASYNC16(dst + so,           gKf + (size_t)(col0 + lrow) * DH + ch * 8);
            CP_ASYNC16(dst + A2_TILE + so, gVf + (size_t)lrow * L_ + col0 + ch * 8);
        }
    }
    CP_COMMIT();
    if (tid < 64) ((int*)(sm + A2_SK))[tid] = seq_id[b * L_ + tlo * 64 + tid];
    int sq0 = seq_id[b * L_ + row0 + w * 16 + (lane >> 2)];
    int sq1 = seq_id[b * L_ + row0 + w * 16 + (lane >> 2) + 8];

    CP_WAIT1();
    __syncthreads();

    // ---- extract Q fragments (held for whole kernel) ----
    uint32_t qf[4][4];
    {
        const __half* sQ = (const __half*)(sm + A2_Q);
        #pragma unroll
        for (int s = 0; s < 4; s++) {
            int base = (w * 16 + (lane >> 2)) * KPAD + s * 16 + (lane & 3) * 2;
            qf[s][0] = *(const uint32_t*)(sQ + base);
            qf[s][1] = *(const uint32_t*)(sQ + base + 8 * KPAD);
            qf[s][2] = *(const uint32_t*)(sQ + base + 8);
            qf[s][3] = *(const uint32_t*)(sQ + base + 8 * KPAD + 8);
        }
    }

    float m0 = -1e30f, m1 = -1e30f, l0 = 0.f, l1 = 0.f;
    float pv[8][4];
    #pragma unroll
    for (int j = 0; j < 8; j++)
        #pragma unroll
        for (int r = 0; r < 4; r++) pv[j][r] = 0.f;

    for (int it = tlo; it <= thi; it++) {
        int buf = (it - tlo) & 1;
        CP_WAIT0();
        __syncthreads();

        // prefetch next tile into other buffer
        if (it + 1 <= thi) {
            int col0n = (it + 1) * 64;
            uint32_t dst = sbase + A2_KV + (buf ^ 1) * A2_BUF;
            #pragma unroll
            for (int c = 0; c < 4; c++) {
                int ch = cb0 + c;
                uint32_t so = (uint32_t)(lrow * KPAD + ch * 8) * 2;
                CP_ASYNC16(dst + so,           gKf + (size_t)(col0n + lrow) * DH + ch * 8);
                CP_ASYNC16(dst + A2_TILE + so, gVf + (size_t)lrow * L_ + col0n + ch * 8);
            }
            if (tid < 64)
                ((int*)(sm + A2_SK))[(buf ^ 1) * 64 + tid] =
                    seq_id[b * L_ + col0n + tid];
        }
        CP_COMMIT();

        const __half* sK = (const __half*)(sm + A2_KV + buf * A2_BUF);
        const __half* sV = sK + A2_TILE / 2;
        const int* skp = (const int*)(sm + A2_SK) + buf * 64;

        // ---- S = Q K^T (fp16 single) ----
        float sf[8][4];
        #pragma unroll
        for (int j = 0; j < 8; j++)
            #pragma unroll
            for (int r = 0; r < 4; r++) sf[j][r] = 0.f;
        #pragma unroll
        for (int s = 0; s < 4; s++) {
            #pragma unroll
            for (int j = 0; j < 8; j++) {
                int off = (j * 8 + (lane >> 2)) * KPAD + s * 16 + (lane & 3) * 2;
                uint32_t bf[2] = {*(const uint32_t*)(sK + off),
                                  *(const uint32_t*)(sK + off + 8)};
                MMAF16(sf[j], qf[s], bf);
            }
        }

        // ---- mask + online softmax (c-frag layout) ----
        int colb = (lane & 3) * 2;
        float nm0 = m0, nm1 = m1;
        #pragma unroll
        for (int j = 0; j < 8; j++) {
            int k0 = skp[8 * j + colb], k1 = skp[8 * j + colb + 1];
            sf[j][0] = (k0 == sq0) ? sf[j][0] : -2e30f;
            sf[j][1] = (k1 == sq0) ? sf[j][1] : -2e30f;
            sf[j][2] = (k0 == sq1) ? sf[j][2] : -2e30f;
            sf[j][3] = (k1 == sq1) ? sf[j][3] : -2e30f;
            nm0 = fmaxf(nm0, fmaxf(sf[j][0], sf[j][1]));
            nm1 = fmaxf(nm1, fmaxf(sf[j][2], sf[j][3]));
        }
        nm0 = fmaxf(nm0, __shfl_xor_sync(0xffffffffu, nm0, 1));
        nm0 = fmaxf(nm0, __shfl_xor_sync(0xffffffffu, nm0, 2));
        nm1 = fmaxf(nm1, __shfl_xor_sync(0xffffffffu, nm1, 1));
        nm1 = fmaxf(nm1, __shfl_xor_sync(0xffffffffu, nm1, 2));
        float a0 = __expf(m0 - nm0), a1 = __expf(m1 - nm1);
        m0 = nm0; m1 = nm1;

        float s0 = 0.f, s1 = 0.f;
        uint32_t ph[4][4];
        #pragma unroll
        for (int j = 0; j < 8; j++) {
            float p0 = __expf(sf[j][0] - m0), p1 = __expf(sf[j][1] - m0);
            float p2 = __expf(sf[j][2] - m1), p3 = __expf(sf[j][3] - m1);
            s0 += p0 + p1; s1 += p2 + p3;
            __half2 h01 = __floats2half2_rn(p0, p1);
            __half2 h23 = __floats2half2_rn(p2, p3);
            int s_ = j >> 1;
            int o  = (j & 1) * 2;
            ph[s_][o]     = *(uint32_t*)&h01;
            ph[s_][o + 1] = *(uint32_t*)&h23;
        }
        s0 += __shfl_xor_sync(0xffffffffu, s0, 1);
        s0 += __shfl_xor_sync(0xffffffffu, s0, 2);
        s1 += __shfl_xor_sync(0xffffffffu, s1, 1);
        s1 += __shfl_xor_sync(0xffffffffu, s1, 2);
        l0 = l0 * a0 + s0;
        l1 = l1 * a1 + s1;
        #pragma unroll
        for (int j = 0; j < 8; j++) {
            pv[j][0] *= a0; pv[j][1] *= a0; pv[j][2] *= a1; pv[j][3] *= a1;
        }

        // ---- PV (fp16 single), B = Vt[dh][c] ----
        #pragma unroll
        for (int s = 0; s < 4; s++) {
            #pragma unroll
            for (int j = 0; j < 8; j++) {
                int off = (j * 8 + (lane >> 2)) * KPAD + s * 16 + (lane & 3) * 2;
                uint32_t bf[2] = {*(const uint32_t*)(sV + off),
                                  *(const uint32_t*)(sV + off + 8)};
                MMAF16(pv[j], ph[s], bf);
            }
        }
    }

    // ---- epilogue: ctx / l -> fp16 [B,L,H,DH] ----
    float inv0 = 1.0f / l0, inv1 = 1.0f / l1;
    int r0g = row0 + w * 16 + (lane >> 2);
    #pragma unroll
    for (int j = 0; j < 8; j++) {
        int c = 8 * j + (lane & 3) * 2;
        size_t o0 = (((size_t)b * L_ + r0g) * H_ + h) * DH + c;
        size_t o1 = (((size_t)b * L_ + r0g + 8) * H_ + h) * DH + c;
        __half2 hx = __floats2half2_rn(pv[j][0] * inv0, pv[j][1] * inv0);
        __half2 hy = __floats2half2_rn(pv[j][2] * inv1, pv[j][3] * inv1);
        *(uint32_t*)&g_cf[o0] = *(uint32_t*)&hx;
        *(uint32_t*)&g_cf[o1] = *(uint32_t*)&hy;
    }
}

// ---------------- launch ----------------
extern "C" void kernel_launch(void* const* d_in, const int* in_sizes, int n_in,
                              void* d_out, int out_size) {
    const float* x      = (const float*)d_in[0];
    const int*   seq_id = (const int*)  d_in[1];
    const float* ln1_w  = (const float*)d_in[2];
    const float* ln1_b  = (const float*)d_in[3];
    const float* w_qkv  = (const float*)d_in[4];
    const float* q_ln_w = (const float*)d_in[5];
    const float* k_ln_w = (const float*)d_in[6];
    const float* out_w  = (const float*)d_in[7];
    float* out = (float*)d_out;

    void *phf, *pwqf, *powf, *pcf, *pqkv;
    cudaGetSymbolAddress(&phf,  g_hf);
    cudaGetSymbolAddress(&pwqf, g_wqf);
    cudaGetSymbolAddress(&powf, g_owf);
    cudaGetSymbolAddress(&pcf,  g_cf);
    cudaGetSymbolAddress(&pqkv, g_qkv);

    cudaFuncSetAttribute(attn_mma, cudaFuncAttributeMaxDynamicSharedMemorySize,
                         ATT3_SMEM);
    cudaFuncSetAttribute(gemm_f16, cudaFuncAttributeMaxDynamicSharedMemorySize,
                         GEMM_SMEM_BYTES);

    prep_kernel<<<8448, 256>>>(x, ln1_w, ln1_b, w_qkv, out_w);
    gemm_f16<<<dim3(D3 / 128, NT / 128), 256, GEMM_SMEM_BYTES>>>(
        (const __half*)phf, (const __half*)pwqf, (float*)pqkv, NT, D3, D_);
    qkrope_vt_kernel<<<6144, 256>>>(q_ln_w, k_ln_w);
    attn_mma<<<dim3(L_ / 64, H_, B_), 128, ATT3_SMEM>>>(seq_id);
    gemm_f16<<<dim3(D_ / 128, NT / 128), 256, GEMM_SMEM_BYTES>>>(
        (const __half*)pcf, (const __half*)powf, out, NT, D_, D_);
}